// round 1
// baseline (speedup 1.0000x reference)
#include <cuda_runtime.h>

#define T_STEPS 128
#define BATCH   32
#define DIM     1024
#define HID     1024
#define G4      4096            // 4*HID
#define M_TOT   4096            // T_STEPS*BATCH
#define HS_PITCH 1025           // padded h row in smem (conflict-free lane-striped reads)

// ---------------- device scratch (static: no allocations allowed) ----------------
__device__ float g_P[(size_t)M_TOT * G4];   // 64MB: precomputed x@Wx + b
__device__ float g_hb[2 * BATCH * HID];     // double-buffered hidden state
__device__ float g_c[BATCH * HID];          // cell state

// ---------------- packed fp32x2 helpers (Blackwell FFMA2) ----------------
__device__ __forceinline__ unsigned long long pack2f(float x, float y) {
    unsigned long long r;
    asm("mov.b64 %0, {%1, %2};" : "=l"(r) : "f"(x), "f"(y));
    return r;
}
__device__ __forceinline__ void unpack2f(unsigned long long v, float& x, float& y) {
    asm("mov.b64 {%0, %1}, %2;" : "=f"(x), "=f"(y) : "l"(v));
}
__device__ __forceinline__ void ffma2(unsigned long long& d, unsigned long long a, unsigned long long b) {
    asm("fma.rn.f32x2 %0, %1, %2, %0;" : "+l"(d) : "l"(a), "l"(b));
}

__device__ __forceinline__ float sigm(float x) { return 1.f / (1.f + __expf(-x)); }

// ---------------- init: zero states ----------------
__global__ void init_state() {
    int i = blockIdx.x * blockDim.x + threadIdx.x;
    if (i < 2 * BATCH * HID) g_hb[i] = 0.f;
    if (i < BATCH * HID)     g_c[i]  = 0.f;
}

// ---------------- SGEMM: g_P = X[4096,1024] @ Wx[1024,4096] + bias ----------------
#define BM 64
#define BN 128
#define BKD 8
__global__ __launch_bounds__(256) void sgemm_xw(const float* __restrict__ A,
                                                const float* __restrict__ B,
                                                const float* __restrict__ bias) {
    __shared__ float As[BKD][BM];
    __shared__ float Bs[BKD][BN];
    int tid  = threadIdx.x;
    int brow = blockIdx.y, bcol = blockIdx.x;

    // load mapping
    int ar = tid >> 1, ac = (tid & 1) * 4;          // A tile: 64 x 8 (threads 0..127)
    int br = tid >> 5, bc = (tid & 31) * 4;         // B tile: 8 x 128 (all threads)
    const float* Ap = A + (size_t)(brow * BM + ar) * DIM + ac;
    const float* Bp = B + (size_t)br * G4 + bcol * BN + bc;

    // compute mapping: 16x16 threads, each 4 rows x (4 + 4) cols
    int trow4 = (tid >> 4) * 4;
    int tcol4 = (tid & 15) * 4;

    unsigned long long acc[4][4] = {};   // [row][colpair]: cols tcol4,+1 | +2,+3 | 64+tcol4,+1 | +2,+3

    for (int k0 = 0; k0 < DIM; k0 += BKD) {
        float4 b4 = *(const float4*)(Bp + (size_t)k0 * G4);
        float4 a4;
        if (tid < 128) a4 = *(const float4*)(Ap + k0);
        __syncthreads();   // WAR guard on smem tiles
        if (tid < 128) {
            As[ac + 0][ar] = a4.x; As[ac + 1][ar] = a4.y;
            As[ac + 2][ar] = a4.z; As[ac + 3][ar] = a4.w;
        }
        *(float4*)&Bs[br][bc] = b4;
        __syncthreads();

        #pragma unroll
        for (int k = 0; k < BKD; k++) {
            float4 mv = *(const float4*)&As[k][trow4];
            ulonglong2 n0 = *(const ulonglong2*)&Bs[k][tcol4];
            ulonglong2 n1 = *(const ulonglong2*)&Bs[k][64 + tcol4];
            float m[4] = {mv.x, mv.y, mv.z, mv.w};
            #pragma unroll
            for (int i = 0; i < 4; i++) {
                unsigned long long mm = pack2f(m[i], m[i]);
                ffma2(acc[i][0], mm, n0.x);
                ffma2(acc[i][1], mm, n0.y);
                ffma2(acc[i][2], mm, n1.x);
                ffma2(acc[i][3], mm, n1.y);
            }
        }
    }

    int row0 = brow * BM + trow4;
    int col0 = bcol * BN + tcol4;
    float4 bias0 = *(const float4*)&bias[col0];
    float4 bias1 = *(const float4*)&bias[col0 + 64];
    #pragma unroll
    for (int i = 0; i < 4; i++) {
        float4 v0, v1;
        unpack2f(acc[i][0], v0.x, v0.y); unpack2f(acc[i][1], v0.z, v0.w);
        unpack2f(acc[i][2], v1.x, v1.y); unpack2f(acc[i][3], v1.z, v1.w);
        v0.x += bias0.x; v0.y += bias0.y; v0.z += bias0.z; v0.w += bias0.w;
        v1.x += bias1.x; v1.y += bias1.y; v1.z += bias1.z; v1.w += bias1.w;
        *(float4*)&g_P[(size_t)(row0 + i) * G4 + col0]      = v0;
        *(float4*)&g_P[(size_t)(row0 + i) * G4 + col0 + 64] = v1;
    }
}

// ---------------- one LSTM timestep ----------------
// grid = 128 blocks (each owns 8 hidden units -> 32 gate columns), 256 threads.
// lane (tid&31) = batch; warp (tid>>5) = 4 gate-cols (paired for FFMA2 in Wh's
// native layout). h_{t-1} cached whole in smem (conflict-free striped), Wh staged
// in 64x32 smem tiles (broadcast LDS.128 in the inner loop).
__global__ __launch_bounds__(256) void lstm_step(const float* __restrict__ Wh,
                                                 float* __restrict__ out, int t) {
    extern __shared__ float h_s[];          // [BATCH][HS_PITCH]
    __shared__ float w_s[64][36];           // [k][col] staged Wh tile
    __shared__ float gsm[32][36];           // gates [batch][col]

    int tid = threadIdx.x;
    int j0  = blockIdx.x * 8;

    const float* hsrc = g_hb + (t & 1) * (BATCH * HID);
    float*       hdst = g_hb + ((t + 1) & 1) * (BATCH * HID);

    // fill h_s (scalar: coalesced LDG, conflict-free STS)
    #pragma unroll 4
    for (int i = tid; i < BATCH * HID; i += 256) {
        int b = i >> 10, k = i & 1023;
        h_s[b * HS_PITCH + k] = hsrc[i];
    }

    int lane = tid & 31;                    // batch
    int c0   = (tid >> 5) * 4;              // first of 4 gate-cols for this warp
    int h_base = lane * HS_PITCH;

    unsigned long long acc0 = 0ull, acc1 = 0ull;

    for (int k0 = 0; k0 < HID; k0 += 64) {
        __syncthreads();                    // also orders h_s fill on first iter
        #pragma unroll
        for (int i = 0; i < 8; i++) {
            int idx = tid + i * 256;
            int kk = idx >> 5, c = idx & 31;
            int gcol = ((c >> 3) << 10) + j0 + (c & 7);
            w_s[kk][c] = Wh[(size_t)(k0 + kk) * G4 + gcol];
        }
        __syncthreads();
        #pragma unroll 8
        for (int kk = 0; kk < 64; kk++) {
            ulonglong2 wv = *(const ulonglong2*)&w_s[kk][c0];   // broadcast
            float hv = h_s[h_base + k0 + kk];                    // striped, no conflict
            unsigned long long hh = pack2f(hv, hv);
            ffma2(acc0, hh, wv.x);
            ffma2(acc1, hh, wv.y);
        }
    }

    // gates = acc + P[t,b,:]
    {
        float v0, v1, v2, v3;
        unpack2f(acc0, v0, v1); unpack2f(acc1, v2, v3);
        int gate = c0 >> 3, u0 = c0 & 7;
        int gcol0 = (gate << 10) + j0 + u0;
        float4 p4 = *(const float4*)&g_P[((size_t)t * BATCH + lane) * G4 + gcol0];
        float4 gv = make_float4(v0 + p4.x, v1 + p4.y, v2 + p4.z, v3 + p4.w);
        *(float4*)&gsm[lane][c0] = gv;
    }
    __syncthreads();

    // pointwise cell update: thread -> (batch b, unit u)
    {
        int b = tid >> 3, u = tid & 7;
        float iv = gsm[b][u];
        float fv = gsm[b][8 + u];
        float gv = gsm[b][16 + u];
        float ov = gsm[b][24 + u];
        int idx = b * HID + j0 + u;
        float co = g_c[idx];
        float cn = sigm(fv) * co + sigm(iv) * tanhf(gv);
        float hn = sigm(ov) * tanhf(cn);
        g_c[idx]  = cn;
        hdst[idx] = hn;
        out[((size_t)t * BATCH + b) * HID + j0 + u] = hn;
    }
}

// ---------------- launch ----------------
extern "C" void kernel_launch(void* const* d_in, const int* in_sizes, int n_in,
                              void* d_out, int out_size) {
    const float* x  = (const float*)d_in[0];   // [T,B,D]
    const float* Wx = (const float*)d_in[1];   // [D,4H]
    const float* Wh = (const float*)d_in[2];   // [H,4H]
    const float* b  = (const float*)d_in[3];   // [4H]
    float* out = (float*)d_out;                // [T,B,H]

    size_t sh = (size_t)BATCH * HS_PITCH * sizeof(float);  // 131200 B
    cudaFuncSetAttribute(lstm_step, cudaFuncAttributeMaxDynamicSharedMemorySize, (int)sh);

    init_state<<<256, 256>>>();

    dim3 gg(G4 / BN, M_TOT / BM);   // (32, 64)
    sgemm_xw<<<gg, 256>>>(x, Wx, b);

    for (int t = 0; t < T_STEPS; t++)
        lstm_step<<<HID / 8, 256, sh>>>(Wh, out, t);
}

// round 2
// speedup vs baseline: 2.8918x; 2.8918x over previous
#include <cuda_runtime.h>

#define T_STEPS 128
#define BATCH   32
#define DIM     1024
#define HID     1024
#define G4      4096            // 4*HID
#define M_TOT   4096            // T_STEPS*BATCH
#define NBLK    128             // persistent blocks (<= 148 SMs, 1 block/SM)
#define NTHR    512

// ---------------- device scratch (no allocations allowed) ----------------
__device__ float g_P[(size_t)M_TOT * G4];     // 64MB: x@Wx + b, [t*B+b][4096]
__device__ float g_ht[2 * HID * BATCH];       // double-buffered h, TRANSPOSED [unit][b]
__device__ float g_c[HID * BATCH];            // cell state [unit][b]
__device__ unsigned g_cnt = 0;                // grid barrier arrive count
__device__ volatile unsigned g_gen = 0;       // grid barrier generation

// ---------------- packed fp32x2 helpers (Blackwell FFMA2) ----------------
__device__ __forceinline__ unsigned long long pack2f(float x, float y) {
    unsigned long long r;
    asm("mov.b64 %0, {%1, %2};" : "=l"(r) : "f"(x), "f"(y));
    return r;
}
__device__ __forceinline__ void unpack2f(unsigned long long v, float& x, float& y) {
    asm("mov.b64 {%0, %1}, %2;" : "=f"(x), "=f"(y) : "l"(v));
}
__device__ __forceinline__ void ffma2(unsigned long long& d, unsigned long long a, unsigned long long b) {
    asm("fma.rn.f32x2 %0, %1, %2, %0;" : "+l"(d) : "l"(a), "l"(b));
}
// L1-bypassing load (h changes every step; L1 is incoherent across the grid barrier)
__device__ __forceinline__ float4 ldcv4(const float* p) {
    float4 v;
    asm volatile("ld.global.cv.v4.f32 {%0,%1,%2,%3}, [%4];"
                 : "=f"(v.x), "=f"(v.y), "=f"(v.z), "=f"(v.w) : "l"(p));
    return v;
}
__device__ __forceinline__ float sigm(float x) { return 1.f / (1.f + __expf(-x)); }

// ---------------- software grid barrier (all NBLK blocks co-resident) ----------------
__device__ __forceinline__ void grid_sync() {
    __threadfence();              // release: make this block's stores L2-visible
    __syncthreads();
    if (threadIdx.x == 0) {
        unsigned gen = g_gen;     // read BEFORE arriving
        if (atomicAdd(&g_cnt, 1u) == NBLK - 1u) {
            g_cnt = 0;
            __threadfence();
            g_gen = gen + 1;      // volatile store releases everyone
        } else {
            while (g_gen == gen) { }
        }
    }
    __syncthreads();
}

// ---------------- init: zero states ----------------
__global__ void init_state() {
    int i = blockIdx.x * blockDim.x + threadIdx.x;
    if (i < 2 * HID * BATCH) g_ht[i] = 0.f;
    if (i < HID * BATCH)     g_c[i]  = 0.f;
}

// ---------------- SGEMM: g_P = X[4096,1024] @ Wx[1024,4096] + bias ----------------
#define BM 64
#define BN 128
#define BKD 8
__global__ __launch_bounds__(256) void sgemm_xw(const float* __restrict__ A,
                                                const float* __restrict__ B,
                                                const float* __restrict__ bias) {
    __shared__ float As[BKD][BM];
    __shared__ float Bs[BKD][BN];
    int tid  = threadIdx.x;
    int brow = blockIdx.y, bcol = blockIdx.x;

    int ar = tid >> 1, ac = (tid & 1) * 4;
    int br = tid >> 5, bc = (tid & 31) * 4;
    const float* Ap = A + (size_t)(brow * BM + ar) * DIM + ac;
    const float* Bp = B + (size_t)br * G4 + bcol * BN + bc;

    int trow4 = (tid >> 4) * 4;
    int tcol4 = (tid & 15) * 4;

    unsigned long long acc[4][4] = {};

    for (int k0 = 0; k0 < DIM; k0 += BKD) {
        float4 b4 = *(const float4*)(Bp + (size_t)k0 * G4);
        float4 a4;
        if (tid < 128) a4 = *(const float4*)(Ap + k0);
        __syncthreads();
        if (tid < 128) {
            As[ac + 0][ar] = a4.x; As[ac + 1][ar] = a4.y;
            As[ac + 2][ar] = a4.z; As[ac + 3][ar] = a4.w;
        }
        *(float4*)&Bs[br][bc] = b4;
        __syncthreads();

        #pragma unroll
        for (int k = 0; k < BKD; k++) {
            float4 mv = *(const float4*)&As[k][trow4];
            ulonglong2 n0 = *(const ulonglong2*)&Bs[k][tcol4];
            ulonglong2 n1 = *(const ulonglong2*)&Bs[k][64 + tcol4];
            float m[4] = {mv.x, mv.y, mv.z, mv.w};
            #pragma unroll
            for (int i = 0; i < 4; i++) {
                unsigned long long mm = pack2f(m[i], m[i]);
                ffma2(acc[i][0], mm, n0.x);
                ffma2(acc[i][1], mm, n0.y);
                ffma2(acc[i][2], mm, n1.x);
                ffma2(acc[i][3], mm, n1.y);
            }
        }
    }

    int row0 = brow * BM + trow4;
    int col0 = bcol * BN + tcol4;
    float4 bias0 = *(const float4*)&bias[col0];
    float4 bias1 = *(const float4*)&bias[col0 + 64];
    #pragma unroll
    for (int i = 0; i < 4; i++) {
        float4 v0, v1;
        unpack2f(acc[i][0], v0.x, v0.y); unpack2f(acc[i][1], v0.z, v0.w);
        unpack2f(acc[i][2], v1.x, v1.y); unpack2f(acc[i][3], v1.z, v1.w);
        v0.x += bias0.x; v0.y += bias0.y; v0.z += bias0.z; v0.w += bias0.w;
        v1.x += bias1.x; v1.y += bias1.y; v1.z += bias1.z; v1.w += bias1.w;
        *(float4*)&g_P[(size_t)(row0 + i) * G4 + col0]      = v0;
        *(float4*)&g_P[(size_t)(row0 + i) * G4 + col0 + 64] = v1;
    }
}

// ---------------- persistent LSTM: all 128 timesteps in one kernel ----------------
// 128 blocks x 512 threads. Block owns 8 hidden units (= 32 gate columns);
// its Wh slice (1024 x 32 = 128KB) lives in smem for the WHOLE sequence.
// warp = K-slice of 64; thread = 4 batches x 8 cols -> 16 FFMA2 per k.
// smem: ws 32768 f | red 16*1056 f | gsm 1056 f  => 202,880 B
#define WS_F  32768
#define RED_F (16 * 1056)
#define GSM_F 1056
#define SMEM_BYTES ((WS_F + RED_F + GSM_F) * 4)

__global__ __launch_bounds__(NTHR, 1) void lstm_persist(const float* __restrict__ Wh,
                                                        float* __restrict__ out) {
    extern __shared__ float sm[];
    float* ws  = sm;                   // [k][c]: Wh slice, ws[k*32+c]
    float* red = sm + WS_F;            // [w][c*33+b] partials
    float* gsm = sm + WS_F + RED_F;    // [c*33+b] gates

    const int tid = threadIdx.x;
    const int j0  = blockIdx.x * 8;    // first hidden unit owned by this block

    // stage Wh slice once: ws[k*32+c] = Wh[k*4096 + (c>>3)*1024 + j0 + (c&7)]
    #pragma unroll
    for (int i = 0; i < 16; i++) {
        int fid = tid + i * NTHR;      // float4 id, 0..8191
        int kk = fid >> 3;
        int cp = fid & 7;
        float4 v = *(const float4*)(Wh + (size_t)kk * G4 + (cp >> 1) * 1024 + j0 + (cp & 1) * 4);
        *(float4*)(ws + kk * 32 + cp * 4) = v;
    }
    __syncthreads();

    const int w    = tid >> 5;         // warp id: K-slice [w*64, w*64+64)
    const int lane = tid & 31;
    const int bg = lane & 7, cg = lane >> 3;
    const int b0 = bg * 4, c0 = cg * 8;
    const int kw = w * 64;

    for (int t = 0; t < T_STEPS; t++) {
        const float* hc = g_ht + (t & 1) * (HID * BATCH);
        float*       hn = g_ht + ((t + 1) & 1) * (HID * BATCH);

        unsigned long long acc[4][4];
        #pragma unroll
        for (int b = 0; b < 4; b++)
            #pragma unroll
            for (int p = 0; p < 4; p++) acc[b][p] = 0ull;

        // software-pipelined h loads (2 groups of 4 k's in flight)
        float4 hb[2][4];
        #pragma unroll
        for (int g = 0; g < 2; g++)
            #pragma unroll
            for (int j = 0; j < 4; j++)
                hb[g][j] = ldcv4(hc + (kw + g * 4 + j) * 32 + b0);

        #pragma unroll
        for (int g = 0; g < 16; g++) {
            float4 h4[4];
            #pragma unroll
            for (int j = 0; j < 4; j++) h4[j] = hb[g & 1][j];
            if (g < 14) {
                #pragma unroll
                for (int j = 0; j < 4; j++)
                    hb[g & 1][j] = ldcv4(hc + (kw + (g + 2) * 4 + j) * 32 + b0);
            }
            #pragma unroll
            for (int j = 0; j < 4; j++) {
                const int k = kw + g * 4 + j;
                ulonglong2 w0 = *(const ulonglong2*)(ws + k * 32 + c0);      // broadcast LDS.128
                ulonglong2 w1 = *(const ulonglong2*)(ws + k * 32 + c0 + 4);
                float hv[4] = {h4[j].x, h4[j].y, h4[j].z, h4[j].w};
                #pragma unroll
                for (int b = 0; b < 4; b++) {
                    unsigned long long hh = pack2f(hv[b], hv[b]);
                    ffma2(acc[b][0], hh, w0.x);
                    ffma2(acc[b][1], hh, w0.y);
                    ffma2(acc[b][2], hh, w1.x);
                    ffma2(acc[b][3], hh, w1.y);
                }
            }
        }

        // cross-warp K reduction via smem
        #pragma unroll
        for (int b = 0; b < 4; b++)
            #pragma unroll
            for (int p = 0; p < 4; p++) {
                float x, y;
                unpack2f(acc[b][p], x, y);
                red[w * 1056 + (c0 + 2 * p)     * 33 + b0 + b] = x;
                red[w * 1056 + (c0 + 2 * p + 1) * 33 + b0 + b] = y;
            }
        __syncthreads();

        // final sum + P; output id: b = oid>>5, c = oid&31
        #pragma unroll
        for (int o = 0; o < 2; o++) {
            int oid = tid + o * NTHR;
            int b = oid >> 5, c = oid & 31;
            float s = 0.f;
            #pragma unroll
            for (int ww = 0; ww < 16; ww++) s += red[ww * 1056 + c * 33 + b];
            s += g_P[((size_t)t * BATCH + b) * G4 + (c >> 3) * 1024 + j0 + (c & 7)];
            gsm[c * 33 + b] = s;
        }
        __syncthreads();

        // pointwise LSTM cell update for the 8 owned units
        if (tid < 256) {
            int u = tid >> 5, b = tid & 31;
            float iv = gsm[(0 * 8 + u) * 33 + b];
            float fv = gsm[(1 * 8 + u) * 33 + b];
            float gv = gsm[(2 * 8 + u) * 33 + b];
            float ov = gsm[(3 * 8 + u) * 33 + b];
            int idx = (j0 + u) * BATCH + b;
            float co = g_c[idx];
            float cn = sigm(fv) * co + sigm(iv) * tanhf(gv);
            float hnv = sigm(ov) * tanhf(cn);
            g_c[idx] = cn;
            hn[idx]  = hnv;
            out[((size_t)t * BATCH + b) * HID + j0 + u] = hnv;
        }

        grid_sync();   // release h_next to all blocks; acquire everyone else's
    }
}

// ---------------- launch ----------------
extern "C" void kernel_launch(void* const* d_in, const int* in_sizes, int n_in,
                              void* d_out, int out_size) {
    const float* x  = (const float*)d_in[0];   // [T,B,D]
    const float* Wx = (const float*)d_in[1];   // [D,4H]
    const float* Wh = (const float*)d_in[2];   // [H,4H]
    const float* b  = (const float*)d_in[3];   // [4H]
    float* out = (float*)d_out;                // [T,B,H]

    cudaFuncSetAttribute(lstm_persist, cudaFuncAttributeMaxDynamicSharedMemorySize, SMEM_BYTES);

    init_state<<<256, 256>>>();

    dim3 gg(G4 / BN, M_TOT / BM);   // (32, 64)
    sgemm_xw<<<gg, 256>>>(x, Wx, b);

    lstm_persist<<<NBLK, NTHR, SMEM_BYTES>>>(Wh, out);
}

// round 3
// speedup vs baseline: 3.2986x; 1.1407x over previous
#include <cuda_runtime.h>

#define T_STEPS 128
#define BATCH   32
#define DIM     1024
#define HID     1024
#define G4      4096            // 4*HID
#define M_TOT   4096            // T_STEPS*BATCH
#define NBLK    128             // persistent blocks (<= 148 SMs, 1 block/SM)
#define NTHR    512

// ---------------- device scratch (no allocations allowed) ----------------
__device__ float g_P[(size_t)M_TOT * G4];     // 64MB: x@Wx + b, [t*B+b][4096]
__device__ float g_ht[2 * HID * BATCH];       // double-buffered h, TRANSPOSED [unit][b]
__device__ float g_c[HID * BATCH];            // cell state [unit][b]
__device__ unsigned g_cnt = 0;                // grid barrier arrive count
__device__ volatile unsigned g_gen = 0;       // grid barrier generation

// ---------------- packed fp32x2 helpers (Blackwell FFMA2) ----------------
__device__ __forceinline__ unsigned long long pack2f(float x, float y) {
    unsigned long long r;
    asm("mov.b64 %0, {%1, %2};" : "=l"(r) : "f"(x), "f"(y));
    return r;
}
__device__ __forceinline__ void unpack2f(unsigned long long v, float& x, float& y) {
    asm("mov.b64 {%0, %1}, %2;" : "=f"(x), "=f"(y) : "l"(v));
}
__device__ __forceinline__ void ffma2(unsigned long long& d, unsigned long long a, unsigned long long b) {
    asm("fma.rn.f32x2 %0, %1, %2, %0;" : "+l"(d) : "l"(a), "l"(b));
}
// L1-bypassing load (h changes every step; L1 is incoherent across the grid barrier)
__device__ __forceinline__ float4 ldcv4(const float* p) {
    float4 v;
    asm volatile("ld.global.cv.v4.f32 {%0,%1,%2,%3}, [%4];"
                 : "=f"(v.x), "=f"(v.y), "=f"(v.z), "=f"(v.w) : "l"(p));
    return v;
}
__device__ __forceinline__ float sigm(float x) { return 1.f / (1.f + __expf(-x)); }

// ---------------- software grid barrier (all NBLK blocks co-resident) ----------------
__device__ __forceinline__ void grid_sync() {
    __threadfence();              // release: make this block's stores L2-visible
    __syncthreads();
    if (threadIdx.x == 0) {
        unsigned gen = g_gen;     // read BEFORE arriving
        if (atomicAdd(&g_cnt, 1u) == NBLK - 1u) {
            g_cnt = 0;
            __threadfence();
            g_gen = gen + 1;      // volatile store releases everyone
        } else {
            while (g_gen == gen) { }
        }
    }
    __syncthreads();
}

// ---------------- init: zero states ----------------
__global__ void init_state() {
    int i = blockIdx.x * blockDim.x + threadIdx.x;
    if (i < 2 * HID * BATCH) g_ht[i] = 0.f;
    if (i < HID * BATCH)     g_c[i]  = 0.f;
}

// ---------------- SGEMM: g_P = X[4096,1024] @ Wx[1024,4096] + bias ----------------
// 128x128 tile, BK=8, 256 threads, 8x8 per thread, double-buffered smem,
// ONE __syncthreads per k-slab, register-prefetched global loads.
#define BM2 128
#define BN2 128
#define BK2 8
#define APITCH 132   // padded As row (kills 2-way STS conflict on the transpose stage)

__global__ __launch_bounds__(256, 2) void sgemm_xw(const float* __restrict__ A,
                                                   const float* __restrict__ B,
                                                   const float* __restrict__ bias) {
    __shared__ float As[2][BK2][APITCH];
    __shared__ float Bs[2][BK2][BN2];

    const int tid  = threadIdx.x;
    const int brow = blockIdx.y, bcol = blockIdx.x;

    // global-load mapping (one float4 of A and one of B per thread per slab)
    const int ar = tid >> 1, ac = (tid & 1) * 4;     // A: 128 rows x 8 k
    const int bkr = tid >> 5, bc = (tid & 31) * 4;   // B: 8 k x 128 cols
    const float* Ap = A + (size_t)(brow * BM2 + ar) * DIM + ac;
    const float* Bp = B + (size_t)bkr * G4 + bcol * BN2 + bc;

    // compute mapping: 16x16 threads, each 8 rows (ty*4+i, 64+ty*4+i) x 8 cols
    const int ty = tid >> 4, tx = tid & 15;

    unsigned long long acc[8][4] = {};   // [m][npair]

    // preload slab 0
    {
        float4 a4 = *(const float4*)Ap;
        float4 b4 = *(const float4*)Bp;
        As[0][ac + 0][ar] = a4.x; As[0][ac + 1][ar] = a4.y;
        As[0][ac + 2][ar] = a4.z; As[0][ac + 3][ar] = a4.w;
        *(float4*)&Bs[0][bkr][bc] = b4;
    }
    __syncthreads();

    const int NSLAB = DIM / BK2;   // 128
    for (int s = 0; s < NSLAB; s++) {
        const int buf = s & 1;
        float4 na4, nb4;
        if (s < NSLAB - 1) {
            na4 = *(const float4*)(Ap + (s + 1) * BK2);
            nb4 = *(const float4*)(Bp + (size_t)(s + 1) * BK2 * G4);
        }

        #pragma unroll
        for (int k = 0; k < BK2; k++) {
            float4 m0 = *(const float4*)&As[buf][k][ty * 4];
            float4 m1 = *(const float4*)&As[buf][k][64 + ty * 4];
            ulonglong2 n0 = *(const ulonglong2*)&Bs[buf][k][tx * 4];
            ulonglong2 n1 = *(const ulonglong2*)&Bs[buf][k][64 + tx * 4];
            float mv[8] = {m0.x, m0.y, m0.z, m0.w, m1.x, m1.y, m1.z, m1.w};
            unsigned long long np[4] = {n0.x, n0.y, n1.x, n1.y};
            #pragma unroll
            for (int i = 0; i < 8; i++) {
                unsigned long long mm = pack2f(mv[i], mv[i]);
                #pragma unroll
                for (int p = 0; p < 4; p++) ffma2(acc[i][p], mm, np[p]);
            }
        }

        if (s < NSLAB - 1) {
            const int nb = buf ^ 1;
            As[nb][ac + 0][ar] = na4.x; As[nb][ac + 1][ar] = na4.y;
            As[nb][ac + 2][ar] = na4.z; As[nb][ac + 3][ar] = na4.w;
            *(float4*)&Bs[nb][bkr][bc] = nb4;
            __syncthreads();
        }
    }

    // epilogue: += bias, store 8x8
    const int col0 = bcol * BN2 + tx * 4;
    float4 bias0 = *(const float4*)&bias[col0];
    float4 bias1 = *(const float4*)&bias[col0 + 64];
    #pragma unroll
    for (int i = 0; i < 8; i++) {
        int row = brow * BM2 + ((i < 4) ? (ty * 4 + i) : (64 + ty * 4 + i - 4));
        float4 v0, v1;
        unpack2f(acc[i][0], v0.x, v0.y); unpack2f(acc[i][1], v0.z, v0.w);
        unpack2f(acc[i][2], v1.x, v1.y); unpack2f(acc[i][3], v1.z, v1.w);
        v0.x += bias0.x; v0.y += bias0.y; v0.z += bias0.z; v0.w += bias0.w;
        v1.x += bias1.x; v1.y += bias1.y; v1.z += bias1.z; v1.w += bias1.w;
        *(float4*)&g_P[(size_t)row * G4 + col0]      = v0;
        *(float4*)&g_P[(size_t)row * G4 + col0 + 64] = v1;
    }
}

// ---------------- persistent LSTM: all 128 timesteps in one kernel ----------------
// 128 blocks x 512 threads. Block owns 8 hidden units (= 32 gate columns);
// its Wh slice (1024 x 32 = 128KB) lives in smem for the WHOLE sequence.
#define WS_F  32768
#define RED_F (16 * 1056)
#define GSM_F 1056
#define SMEM_BYTES ((WS_F + RED_F + GSM_F) * 4)

__global__ __launch_bounds__(NTHR, 1) void lstm_persist(const float* __restrict__ Wh,
                                                        float* __restrict__ out) {
    extern __shared__ float sm[];
    float* ws  = sm;                   // [k][c]: Wh slice, ws[k*32+c]
    float* red = sm + WS_F;            // [w][c*33+b] partials
    float* gsm = sm + WS_F + RED_F;    // [c*33+b] gates

    const int tid = threadIdx.x;
    const int j0  = blockIdx.x * 8;    // first hidden unit owned by this block

    // stage Wh slice once
    #pragma unroll
    for (int i = 0; i < 16; i++) {
        int fid = tid + i * NTHR;
        int kk = fid >> 3;
        int cp = fid & 7;
        float4 v = *(const float4*)(Wh + (size_t)kk * G4 + (cp >> 1) * 1024 + j0 + (cp & 1) * 4);
        *(float4*)(ws + kk * 32 + cp * 4) = v;
    }
    __syncthreads();

    const int w    = tid >> 5;
    const int lane = tid & 31;
    const int bg = lane & 7, cg = lane >> 3;
    const int b0 = bg * 4, c0 = cg * 8;
    const int kw = w * 64;

    // P-address precompute for the reduce phase (2 outputs per thread)
    const int ob0 = tid >> 5,          oc0 = tid & 31;
    const int ob1 = (tid + NTHR) >> 5, oc1 = (tid + NTHR) & 31;
    const size_t pofs0 = (size_t)ob0 * G4 + (oc0 >> 3) * 1024 + j0 + (oc0 & 7);
    const size_t pofs1 = (size_t)ob1 * G4 + (oc1 >> 3) * 1024 + j0 + (oc1 & 7);

    for (int t = 0; t < T_STEPS; t++) {
        const float* hc = g_ht + (t & 1) * (HID * BATCH);
        float*       hn = g_ht + ((t + 1) & 1) * (HID * BATCH);

        // prefetch P for this step (hidden behind the GEMM below)
        float p0 = g_P[(size_t)t * BATCH * G4 + pofs0];
        float p1 = g_P[(size_t)t * BATCH * G4 + pofs1];

        unsigned long long acc[4][4];
        #pragma unroll
        for (int b = 0; b < 4; b++)
            #pragma unroll
            for (int p = 0; p < 4; p++) acc[b][p] = 0ull;

        // software-pipelined h loads (2 groups of 4 k's in flight)
        float4 hb[2][4];
        #pragma unroll
        for (int g = 0; g < 2; g++)
            #pragma unroll
            for (int j = 0; j < 4; j++)
                hb[g][j] = ldcv4(hc + (kw + g * 4 + j) * 32 + b0);

        #pragma unroll
        for (int g = 0; g < 16; g++) {
            float4 h4[4];
            #pragma unroll
            for (int j = 0; j < 4; j++) h4[j] = hb[g & 1][j];
            if (g < 14) {
                #pragma unroll
                for (int j = 0; j < 4; j++)
                    hb[g & 1][j] = ldcv4(hc + (kw + (g + 2) * 4 + j) * 32 + b0);
            }
            #pragma unroll
            for (int j = 0; j < 4; j++) {
                const int k = kw + g * 4 + j;
                ulonglong2 w0 = *(const ulonglong2*)(ws + k * 32 + c0);
                ulonglong2 w1 = *(const ulonglong2*)(ws + k * 32 + c0 + 4);
                float hv[4] = {h4[j].x, h4[j].y, h4[j].z, h4[j].w};
                #pragma unroll
                for (int b = 0; b < 4; b++) {
                    unsigned long long hh = pack2f(hv[b], hv[b]);
                    ffma2(acc[b][0], hh, w0.x);
                    ffma2(acc[b][1], hh, w0.y);
                    ffma2(acc[b][2], hh, w1.x);
                    ffma2(acc[b][3], hh, w1.y);
                }
            }
        }

        // cross-warp K reduction via smem
        #pragma unroll
        for (int b = 0; b < 4; b++)
            #pragma unroll
            for (int p = 0; p < 4; p++) {
                float x, y;
                unpack2f(acc[b][p], x, y);
                red[w * 1056 + (c0 + 2 * p)     * 33 + b0 + b] = x;
                red[w * 1056 + (c0 + 2 * p + 1) * 33 + b0 + b] = y;
            }
        __syncthreads();

        // final sum + prefetched P
        {
            float s0 = 0.f, s1 = 0.f;
            #pragma unroll
            for (int ww = 0; ww < 16; ww++) {
                s0 += red[ww * 1056 + oc0 * 33 + ob0];
                s1 += red[ww * 1056 + oc1 * 33 + ob1];
            }
            gsm[oc0 * 33 + ob0] = s0 + p0;
            gsm[oc1 * 33 + ob1] = s1 + p1;
        }
        __syncthreads();

        // pointwise LSTM cell update for the 8 owned units
        if (tid < 256) {
            int u = tid >> 5, b = tid & 31;
            float iv = gsm[(0 * 8 + u) * 33 + b];
            float fv = gsm[(1 * 8 + u) * 33 + b];
            float gv = gsm[(2 * 8 + u) * 33 + b];
            float ov = gsm[(3 * 8 + u) * 33 + b];
            int idx = (j0 + u) * BATCH + b;
            float co = g_c[idx];
            float cn = sigm(fv) * co + sigm(iv) * tanhf(gv);
            float hnv = sigm(ov) * tanhf(cn);
            g_c[idx] = cn;
            hn[idx]  = hnv;
            out[((size_t)t * BATCH + b) * HID + j0 + u] = hnv;
        }

        grid_sync();   // release h_next to all blocks; acquire everyone else's
    }
}

// ---------------- launch ----------------
extern "C" void kernel_launch(void* const* d_in, const int* in_sizes, int n_in,
                              void* d_out, int out_size) {
    const float* x  = (const float*)d_in[0];   // [T,B,D]
    const float* Wx = (const float*)d_in[1];   // [D,4H]
    const float* Wh = (const float*)d_in[2];   // [H,4H]
    const float* b  = (const float*)d_in[3];   // [4H]
    float* out = (float*)d_out;                // [T,B,H]

    cudaFuncSetAttribute(lstm_persist, cudaFuncAttributeMaxDynamicSharedMemorySize, SMEM_BYTES);

    init_state<<<256, 256>>>();

    dim3 gg(G4 / BN2, M_TOT / BM2);   // (32, 32)
    sgemm_xw<<<gg, 256>>>(x, Wx, b);

    lstm_persist<<<NBLK, NTHR, SMEM_BYTES>>>(Wh, out);
}

// round 8
// speedup vs baseline: 3.5750x; 1.0838x over previous
#include <cuda_runtime.h>
#include <cuda_bf16.h>
#include <cstdint>

#define T_STEPS 128
#define BATCH   32
#define DIM     1024
#define HID     1024
#define G4      4096            // 4*HID
#define M_TOT   4096            // T_STEPS*BATCH
#define NBLK    128             // persistent blocks (<= 148 SMs, 1 block/SM)
#define NTHR    512

// ---------------- device scratch (no allocations allowed) ----------------
__device__ float g_P[(size_t)M_TOT * G4];     // 64MB: x@Wx + b
__device__ float g_ht[2 * HID * BATCH];       // double-buffered h, TRANSPOSED [unit][b]
__device__ float g_c[HID * BATCH];            // cell state [unit][b]
__device__ unsigned g_cnt = 0;
__device__ volatile unsigned g_gen = 0;

// ---------------- packed fp32x2 helpers (Blackwell FFMA2) ----------------
__device__ __forceinline__ unsigned long long pack2f(float x, float y) {
    unsigned long long r;
    asm("mov.b64 %0, {%1, %2};" : "=l"(r) : "f"(x), "f"(y));
    return r;
}
__device__ __forceinline__ void unpack2f(unsigned long long v, float& x, float& y) {
    asm("mov.b64 {%0, %1}, %2;" : "=f"(x), "=f"(y) : "l"(v));
}
__device__ __forceinline__ void ffma2(unsigned long long& d, unsigned long long a, unsigned long long b) {
    asm("fma.rn.f32x2 %0, %1, %2, %0;" : "+l"(d) : "l"(a), "l"(b));
}
__device__ __forceinline__ float4 ldcv4(const float* p) {
    float4 v;
    asm volatile("ld.global.cv.v4.f32 {%0,%1,%2,%3}, [%4];"
                 : "=f"(v.x), "=f"(v.y), "=f"(v.z), "=f"(v.w) : "l"(p));
    return v;
}
__device__ __forceinline__ float sigm(float x) { return 1.f / (1.f + __expf(-x)); }

__device__ __forceinline__ void mma_bf16(float* d, const uint32_t* a, const uint32_t* b) {
    asm volatile("mma.sync.aligned.m16n8k16.row.col.f32.bf16.bf16.f32 "
                 "{%0,%1,%2,%3}, {%4,%5,%6,%7}, {%8,%9}, {%0,%1,%2,%3};"
                 : "+f"(d[0]), "+f"(d[1]), "+f"(d[2]), "+f"(d[3])
                 : "r"(a[0]), "r"(a[1]), "r"(a[2]), "r"(a[3]), "r"(b[0]), "r"(b[1]));
}
__device__ __forceinline__ void bf16split(float v, unsigned short& h, unsigned short& l) {
    __nv_bfloat16 hb = __float2bfloat16(v);
    __nv_bfloat16 lb = __float2bfloat16(v - __bfloat162float(hb));
    h = *(unsigned short*)&hb;
    l = *(unsigned short*)&lb;
}

// ---------------- software grid barrier ----------------
__device__ __forceinline__ void grid_sync() {
    __threadfence();
    __syncthreads();
    if (threadIdx.x == 0) {
        unsigned gen = g_gen;
        if (atomicAdd(&g_cnt, 1u) == NBLK - 1u) {
            g_cnt = 0;
            __threadfence();
            g_gen = gen + 1;
        } else {
            while (g_gen == gen) { }
        }
    }
    __syncthreads();
}

// ---------------- init: zero states ----------------
__global__ void init_state() {
    int i = blockIdx.x * blockDim.x + threadIdx.x;
    if (i < 2 * HID * BATCH) g_ht[i] = 0.f;
    if (i < HID * BATCH)     g_c[i]  = 0.f;
}

// ---------------- bf16 split-precision GEMM via mma.sync (no ldmatrix) ----------------
// P = A@B + bias with A,B split in-register to bf16 hi/lo; 3-term product.
// CTA 128x128, 256 thr (8 warps as 2x4 -> 64x32 warp tiles), K-slabs of 32,
// double-buffered smem with register prefetch.
// smem buffer: Ah[128][40bf16] Al Bh[128n][40bf16] Bl  (4 x 10240 B = 40960)
#define GPITCH 40                       // bf16 units per row (80 bytes, 20 banks)
#define GAREA  (128 * GPITCH * 2)       // 10240 bytes
#define GBUF   (4 * GAREA)              // 40960
#define GS_SMEM (2 * GBUF)              // 81920

__global__ __launch_bounds__(256) void sgemm_bf16(const float* __restrict__ A,
                                                  const float* __restrict__ B,
                                                  const float* __restrict__ bias) {
    extern __shared__ char gsm_[];
    const int tid = threadIdx.x;
    const int l   = tid & 31;
    const int wid = tid >> 5;
    const int wm  = wid >> 2, wn = wid & 3;     // 2x4 warp grid
    const int brow = blockIdx.y, bcol = blockIdx.x;

    float4 ra[4], rb[4];

    // load slab s into registers (A: [row][k], B: [k][n] rows)
    auto ldg_slab = [&](int s) {
        const int k0 = s * 32;
        #pragma unroll
        for (int i = 0; i < 4; i++) {
            int id = tid + i * 256;
            int row = id >> 3, q = id & 7;                 // A: 128 rows x 8 quads of k
            ra[i] = *(const float4*)(A + (size_t)(brow * 128 + row) * DIM + k0 + q * 4);
            int k = id & 31, n4 = (id >> 5) * 4;           // B: lane-major k for conflict-free STS
            rb[i] = *(const float4*)(B + (size_t)(k0 + k) * G4 + bcol * 128 + n4);
        }
    };
    // split + store registers into smem buffer b
    auto sts_slab = [&](int b) {
        char* Ah = gsm_ + b * GBUF;
        char* Al = Ah + GAREA;
        char* Bh = Al + GAREA;
        char* Bl = Bh + GAREA;
        #pragma unroll
        for (int i = 0; i < 4; i++) {
            int id = tid + i * 256;
            int row = id >> 3, q = id & 7;
            float fa[4] = {ra[i].x, ra[i].y, ra[i].z, ra[i].w};
            ushort4 h4, l4;
            bf16split(fa[0], h4.x, l4.x); bf16split(fa[1], h4.y, l4.y);
            bf16split(fa[2], h4.z, l4.z); bf16split(fa[3], h4.w, l4.w);
            *(ushort4*)(Ah + row * (GPITCH * 2) + q * 8) = h4;
            *(ushort4*)(Al + row * (GPITCH * 2) + q * 8) = l4;
            int k = id & 31, n4 = (id >> 5) * 4;
            float fb[4] = {rb[i].x, rb[i].y, rb[i].z, rb[i].w};
            #pragma unroll
            for (int j = 0; j < 4; j++) {
                unsigned short h, lo;
                bf16split(fb[j], h, lo);
                *(unsigned short*)(Bh + (n4 + j) * (GPITCH * 2) + k * 2) = h;
                *(unsigned short*)(Bl + (n4 + j) * (GPITCH * 2) + k * 2) = lo;
            }
        }
    };

    float acc[4][4][4];
    #pragma unroll
    for (int mi = 0; mi < 4; mi++)
        #pragma unroll
        for (int ni = 0; ni < 4; ni++)
            #pragma unroll
            for (int q = 0; q < 4; q++) acc[mi][ni][q] = 0.f;

    ldg_slab(0);
    sts_slab(0);
    __syncthreads();

    for (int s = 0; s < 32; s++) {
        if (s < 31) ldg_slab(s + 1);     // LDG latency hidden behind compute

        const int b = s & 1;
        const char* Ah = gsm_ + b * GBUF;
        const char* Al = Ah + GAREA;
        const char* Bh = Al + GAREA;
        const char* Bl = Bh + GAREA;

        #pragma unroll
        for (int ks = 0; ks < 2; ks++) {
            const int kb = ks * 32 + (l & 3) * 4;          // byte offset of this lane's k-pair
            uint32_t ah[4][4], al[4][4], bh[4][2], bl[4][2];
            #pragma unroll
            for (int mi = 0; mi < 4; mi++) {
                const char* p = Ah + (wm * 64 + mi * 16 + (l >> 2)) * (GPITCH * 2) + kb;
                const char* q = Al + (wm * 64 + mi * 16 + (l >> 2)) * (GPITCH * 2) + kb;
                ah[mi][0] = *(const uint32_t*)(p);
                ah[mi][1] = *(const uint32_t*)(p + 8 * GPITCH * 2);
                ah[mi][2] = *(const uint32_t*)(p + 16);
                ah[mi][3] = *(const uint32_t*)(p + 8 * GPITCH * 2 + 16);
                al[mi][0] = *(const uint32_t*)(q);
                al[mi][1] = *(const uint32_t*)(q + 8 * GPITCH * 2);
                al[mi][2] = *(const uint32_t*)(q + 16);
                al[mi][3] = *(const uint32_t*)(q + 8 * GPITCH * 2 + 16);
            }
            #pragma unroll
            for (int ni = 0; ni < 4; ni++) {
                const char* p = Bh + (wn * 32 + ni * 8 + (l >> 2)) * (GPITCH * 2) + kb;
                const char* q = Bl + (wn * 32 + ni * 8 + (l >> 2)) * (GPITCH * 2) + kb;
                bh[ni][0] = *(const uint32_t*)(p);
                bh[ni][1] = *(const uint32_t*)(p + 16);
                bl[ni][0] = *(const uint32_t*)(q);
                bl[ni][1] = *(const uint32_t*)(q + 16);
            }
            #pragma unroll
            for (int mi = 0; mi < 4; mi++)
                #pragma unroll
                for (int ni = 0; ni < 4; ni++) {
                    mma_bf16(acc[mi][ni], ah[mi], bh[ni]);   // hi*hi
                    mma_bf16(acc[mi][ni], ah[mi], bl[ni]);   // hi*lo
                    mma_bf16(acc[mi][ni], al[mi], bh[ni]);   // lo*hi
                }
        }
        __syncthreads();
        if (s < 31) {
            sts_slab((s + 1) & 1);
            __syncthreads();
        }
    }

    // epilogue: lane l -> d0,d1: (row=l>>2, col=2*(l&3)+{0,1}); d2,d3: row+8
    #pragma unroll
    for (int mi = 0; mi < 4; mi++) {
        int row0 = brow * 128 + wm * 64 + mi * 16 + (l >> 2);
        #pragma unroll
        for (int ni = 0; ni < 4; ni++) {
            int col = bcol * 128 + wn * 32 + ni * 8 + 2 * (l & 3);
            float b0 = bias[col], b1 = bias[col + 1];
            float2 v0 = make_float2(acc[mi][ni][0] + b0, acc[mi][ni][1] + b1);
            float2 v1 = make_float2(acc[mi][ni][2] + b0, acc[mi][ni][3] + b1);
            *(float2*)&g_P[(size_t)row0 * G4 + col]       = v0;
            *(float2*)&g_P[(size_t)(row0 + 8) * G4 + col] = v1;
        }
    }
}

// ---------------- persistent LSTM: all 128 timesteps in one kernel ----------------
#define WS_F  32768
#define RED_F (16 * 1056)
#define GSM_F 1056
#define SMEM_BYTES ((WS_F + RED_F + GSM_F) * 4)

__global__ __launch_bounds__(NTHR, 1) void lstm_persist(const float* __restrict__ Wh,
                                                        float* __restrict__ out) {
    extern __shared__ float sm[];
    float* ws  = sm;
    float* red = sm + WS_F;
    float* gsm = sm + WS_F + RED_F;

    const int tid = threadIdx.x;
    const int j0  = blockIdx.x * 8;

    #pragma unroll
    for (int i = 0; i < 16; i++) {
        int fid = tid + i * NTHR;
        int kk = fid >> 3;
        int cp = fid & 7;
        float4 v = *(const float4*)(Wh + (size_t)kk * G4 + (cp >> 1) * 1024 + j0 + (cp & 1) * 4);
        *(float4*)(ws + kk * 32 + cp * 4) = v;
    }
    __syncthreads();

    const int w    = tid >> 5;
    const int lane = tid & 31;
    const int bg = lane & 7, cg = lane >> 3;
    const int b0 = bg * 4, c0 = cg * 8;
    const int kw = w * 64;

    const int ob0 = tid >> 5,          oc0 = tid & 31;
    const int ob1 = (tid + NTHR) >> 5, oc1 = (tid + NTHR) & 31;
    const size_t pofs0 = (size_t)ob0 * G4 + (oc0 >> 3) * 1024 + j0 + (oc0 & 7);
    const size_t pofs1 = (size_t)ob1 * G4 + (oc1 >> 3) * 1024 + j0 + (oc1 & 7);

    for (int t = 0; t < T_STEPS; t++) {
        const float* hc = g_ht + (t & 1) * (HID * BATCH);
        float*       hn = g_ht + ((t + 1) & 1) * (HID * BATCH);

        float p0 = g_P[(size_t)t * BATCH * G4 + pofs0];
        float p1 = g_P[(size_t)t * BATCH * G4 + pofs1];

        unsigned long long acc[4][4];
        #pragma unroll
        for (int b = 0; b < 4; b++)
            #pragma unroll
            for (int p = 0; p < 4; p++) acc[b][p] = 0ull;

        float4 hb[2][4];
        #pragma unroll
        for (int g = 0; g < 2; g++)
            #pragma unroll
            for (int j = 0; j < 4; j++)
                hb[g][j] = ldcv4(hc + (kw + g * 4 + j) * 32 + b0);

        #pragma unroll
        for (int g = 0; g < 16; g++) {
            float4 h4[4];
            #pragma unroll
            for (int j = 0; j < 4; j++) h4[j] = hb[g & 1][j];
            if (g < 14) {
                #pragma unroll
                for (int j = 0; j < 4; j++)
                    hb[g & 1][j] = ldcv4(hc + (kw + (g + 2) * 4 + j) * 32 + b0);
            }
            #pragma unroll
            for (int j = 0; j < 4; j++) {
                const int k = kw + g * 4 + j;
                ulonglong2 w0 = *(const ulonglong2*)(ws + k * 32 + c0);
                ulonglong2 w1 = *(const ulonglong2*)(ws + k * 32 + c0 + 4);
                float hv[4] = {h4[j].x, h4[j].y, h4[j].z, h4[j].w};
                #pragma unroll
                for (int b = 0; b < 4; b++) {
                    unsigned long long hh = pack2f(hv[b], hv[b]);
                    ffma2(acc[b][0], hh, w0.x);
                    ffma2(acc[b][1], hh, w0.y);
                    ffma2(acc[b][2], hh, w1.x);
                    ffma2(acc[b][3], hh, w1.y);
                }
            }
        }

        #pragma unroll
        for (int b = 0; b < 4; b++)
            #pragma unroll
            for (int p = 0; p < 4; p++) {
                float x, y;
                unpack2f(acc[b][p], x, y);
                red[w * 1056 + (c0 + 2 * p)     * 33 + b0 + b] = x;
                red[w * 1056 + (c0 + 2 * p + 1) * 33 + b0 + b] = y;
            }
        __syncthreads();

        {
            float s0 = 0.f, s1 = 0.f;
            #pragma unroll
            for (int ww = 0; ww < 16; ww++) {
                s0 += red[ww * 1056 + oc0 * 33 + ob0];
                s1 += red[ww * 1056 + oc1 * 33 + ob1];
            }
            gsm[oc0 * 33 + ob0] = s0 + p0;
            gsm[oc1 * 33 + ob1] = s1 + p1;
        }
        __syncthreads();

        if (tid < 256) {
            int u = tid >> 5, b = tid & 31;
            float iv = gsm[(0 * 8 + u) * 33 + b];
            float fv = gsm[(1 * 8 + u) * 33 + b];
            float gv = gsm[(2 * 8 + u) * 33 + b];
            float ov = gsm[(3 * 8 + u) * 33 + b];
            int idx = (j0 + u) * BATCH + b;
            float co = g_c[idx];
            float cn = sigm(fv) * co + sigm(iv) * tanhf(gv);
            float hnv = sigm(ov) * tanhf(cn);
            g_c[idx] = cn;
            hn[idx]  = hnv;
            out[((size_t)t * BATCH + b) * HID + j0 + u] = hnv;
        }

        grid_sync();
    }
}

// ---------------- launch ----------------
extern "C" void kernel_launch(void* const* d_in, const int* in_sizes, int n_in,
                              void* d_out, int out_size) {
    const float* x  = (const float*)d_in[0];   // [T,B,D]
    const float* Wx = (const float*)d_in[1];   // [D,4H]
    const float* Wh = (const float*)d_in[2];   // [H,4H]
    const float* b  = (const float*)d_in[3];   // [4H]
    float* out = (float*)d_out;                // [T,B,H]

    cudaFuncSetAttribute(sgemm_bf16, cudaFuncAttributeMaxDynamicSharedMemorySize, GS_SMEM);
    cudaFuncSetAttribute(lstm_persist, cudaFuncAttributeMaxDynamicSharedMemorySize, SMEM_BYTES);

    init_state<<<256, 256>>>();

    dim3 gg(G4 / 128, M_TOT / 128);   // (32, 32)
    sgemm_bf16<<<gg, 256, GS_SMEM>>>(x, Wx, b);

    lstm_persist<<<NBLK, NTHR, SMEM_BYTES>>>(Wh, out);
}

// round 12
// speedup vs baseline: 3.9325x; 1.1000x over previous
#include <cuda_runtime.h>
#include <cuda_bf16.h>
#include <cstdint>

#define T_STEPS 128
#define BATCH   32
#define DIM     1024
#define HID     1024
#define G4      4096            // 4*HID
#define M_TOT   4096            // T_STEPS*BATCH
#define NBLK    128             // persistent blocks (<= 148 SMs, 1 block/SM)
#define NTHR    256

// ---------------- device scratch (no allocations allowed) ----------------
__device__ float g_P[(size_t)M_TOT * G4];   // 64MB: x@Wx + b
// h split to bf16 hi/lo, fragment-major, double buffered.
// uint4 index: [(ks*4 + (b>>3))*32 + (b&7)*4 + cc]  (8192 uint4 per buffer)
// uint4 = {hi2(p0), lo2(p0), hi2(p1), lo2(p1)}, p0 = 8ks+cc, p1 = p0+4 (kpair ids)
__device__ uint4 g_hf[2 * 8192];
__device__ float g_c[HID * BATCH];          // cell state [unit][batch]
__device__ unsigned g_cnt = 0;
__device__ volatile unsigned g_gen = 0;

// ---------------- helpers ----------------
__device__ __forceinline__ float sigm(float x) { return 1.f / (1.f + __expf(-x)); }

__device__ __forceinline__ void mma_bf16(float* d, const uint32_t* a, const uint32_t* b) {
    asm volatile("mma.sync.aligned.m16n8k16.row.col.f32.bf16.bf16.f32 "
                 "{%0,%1,%2,%3}, {%4,%5,%6,%7}, {%8,%9}, {%0,%1,%2,%3};"
                 : "+f"(d[0]), "+f"(d[1]), "+f"(d[2]), "+f"(d[3])
                 : "r"(a[0]), "r"(a[1]), "r"(a[2]), "r"(a[3]), "r"(b[0]), "r"(b[1]));
}
__device__ __forceinline__ void bf16split(float v, unsigned short& h, unsigned short& l) {
    __nv_bfloat16 hb = __float2bfloat16(v);
    __nv_bfloat16 lb = __float2bfloat16(v - __bfloat162float(hb));
    h = *(unsigned short*)&hb;
    l = *(unsigned short*)&lb;
}

// ---------------- software grid barrier ----------------
__device__ __forceinline__ void grid_sync() {
    __threadfence();              // release + L1D invalidate (CCTL.IVALL at gpu scope)
    __syncthreads();
    if (threadIdx.x == 0) {
        unsigned gen = g_gen;
        if (atomicAdd(&g_cnt, 1u) == NBLK - 1u) {
            g_cnt = 0;
            __threadfence();
            g_gen = gen + 1;
        } else {
            while (g_gen == gen) { }
        }
    }
    __syncthreads();
}

// ---------------- init: zero states ----------------
__global__ void init_state() {
    int i = blockIdx.x * blockDim.x + threadIdx.x;
    if (i < 2 * 8192) g_hf[i] = make_uint4(0, 0, 0, 0);
    if (i < HID * BATCH) g_c[i] = 0.f;
}

// ---------------- bf16 split-precision GEMM via mma.sync (R8, verified) ----------------
#define GPITCH 40
#define GAREA  (128 * GPITCH * 2)
#define GBUF   (4 * GAREA)
#define GS_SMEM (2 * GBUF)

__global__ __launch_bounds__(256) void sgemm_bf16(const float* __restrict__ A,
                                                  const float* __restrict__ B,
                                                  const float* __restrict__ bias) {
    extern __shared__ char gsm_[];
    const int tid = threadIdx.x;
    const int l   = tid & 31;
    const int wid = tid >> 5;
    const int wm  = wid >> 2, wn = wid & 3;
    const int brow = blockIdx.y, bcol = blockIdx.x;

    float4 ra[4], rb[4];

    auto ldg_slab = [&](int s) {
        const int k0 = s * 32;
        #pragma unroll
        for (int i = 0; i < 4; i++) {
            int id = tid + i * 256;
            int row = id >> 3, q = id & 7;
            ra[i] = *(const float4*)(A + (size_t)(brow * 128 + row) * DIM + k0 + q * 4);
            int k = id & 31, n4 = (id >> 5) * 4;
            rb[i] = *(const float4*)(B + (size_t)(k0 + k) * G4 + bcol * 128 + n4);
        }
    };
    auto sts_slab = [&](int b) {
        char* Ah = gsm_ + b * GBUF;
        char* Al = Ah + GAREA;
        char* Bh = Al + GAREA;
        char* Bl = Bh + GAREA;
        #pragma unroll
        for (int i = 0; i < 4; i++) {
            int id = tid + i * 256;
            int row = id >> 3, q = id & 7;
            float fa[4] = {ra[i].x, ra[i].y, ra[i].z, ra[i].w};
            ushort4 h4, l4;
            bf16split(fa[0], h4.x, l4.x); bf16split(fa[1], h4.y, l4.y);
            bf16split(fa[2], h4.z, l4.z); bf16split(fa[3], h4.w, l4.w);
            *(ushort4*)(Ah + row * (GPITCH * 2) + q * 8) = h4;
            *(ushort4*)(Al + row * (GPITCH * 2) + q * 8) = l4;
            int k = id & 31, n4 = (id >> 5) * 4;
            float fb[4] = {rb[i].x, rb[i].y, rb[i].z, rb[i].w};
            #pragma unroll
            for (int j = 0; j < 4; j++) {
                unsigned short h, lo;
                bf16split(fb[j], h, lo);
                *(unsigned short*)(Bh + (n4 + j) * (GPITCH * 2) + k * 2) = h;
                *(unsigned short*)(Bl + (n4 + j) * (GPITCH * 2) + k * 2) = lo;
            }
        }
    };

    float acc[4][4][4];
    #pragma unroll
    for (int mi = 0; mi < 4; mi++)
        #pragma unroll
        for (int ni = 0; ni < 4; ni++)
            #pragma unroll
            for (int q = 0; q < 4; q++) acc[mi][ni][q] = 0.f;

    ldg_slab(0);
    sts_slab(0);
    __syncthreads();

    for (int s = 0; s < 32; s++) {
        if (s < 31) ldg_slab(s + 1);

        const int b = s & 1;
        const char* Ah = gsm_ + b * GBUF;
        const char* Al = Ah + GAREA;
        const char* Bh = Al + GAREA;
        const char* Bl = Bh + GAREA;

        #pragma unroll
        for (int ks = 0; ks < 2; ks++) {
            const int kb = ks * 32 + (l & 3) * 4;
            uint32_t ah[4][4], al[4][4], bh[4][2], bl[4][2];
            #pragma unroll
            for (int mi = 0; mi < 4; mi++) {
                const char* p = Ah + (wm * 64 + mi * 16 + (l >> 2)) * (GPITCH * 2) + kb;
                const char* q = Al + (wm * 64 + mi * 16 + (l >> 2)) * (GPITCH * 2) + kb;
                ah[mi][0] = *(const uint32_t*)(p);
                ah[mi][1] = *(const uint32_t*)(p + 8 * GPITCH * 2);
                ah[mi][2] = *(const uint32_t*)(p + 16);
                ah[mi][3] = *(const uint32_t*)(p + 8 * GPITCH * 2 + 16);
                al[mi][0] = *(const uint32_t*)(q);
                al[mi][1] = *(const uint32_t*)(q + 8 * GPITCH * 2);
                al[mi][2] = *(const uint32_t*)(q + 16);
                al[mi][3] = *(const uint32_t*)(q + 8 * GPITCH * 2 + 16);
            }
            #pragma unroll
            for (int ni = 0; ni < 4; ni++) {
                const char* p = Bh + (wn * 32 + ni * 8 + (l >> 2)) * (GPITCH * 2) + kb;
                const char* q = Bl + (wn * 32 + ni * 8 + (l >> 2)) * (GPITCH * 2) + kb;
                bh[ni][0] = *(const uint32_t*)(p);
                bh[ni][1] = *(const uint32_t*)(p + 16);
                bl[ni][0] = *(const uint32_t*)(q);
                bl[ni][1] = *(const uint32_t*)(q + 16);
            }
            #pragma unroll
            for (int mi = 0; mi < 4; mi++)
                #pragma unroll
                for (int ni = 0; ni < 4; ni++) {
                    mma_bf16(acc[mi][ni], ah[mi], bh[ni]);
                    mma_bf16(acc[mi][ni], ah[mi], bl[ni]);
                    mma_bf16(acc[mi][ni], al[mi], bh[ni]);
                }
        }
        __syncthreads();
        if (s < 31) {
            sts_slab((s + 1) & 1);
            __syncthreads();
        }
    }

    #pragma unroll
    for (int mi = 0; mi < 4; mi++) {
        int row0 = brow * 128 + wm * 64 + mi * 16 + (l >> 2);
        #pragma unroll
        for (int ni = 0; ni < 4; ni++) {
            int col = bcol * 128 + wn * 32 + ni * 8 + 2 * (l & 3);
            float b0 = bias[col], b1 = bias[col + 1];
            float2 v0 = make_float2(acc[mi][ni][0] + b0, acc[mi][ni][1] + b1);
            float2 v1 = make_float2(acc[mi][ni][2] + b0, acc[mi][ni][3] + b1);
            *(float2*)&g_P[(size_t)row0 * G4 + col]       = v0;
            *(float2*)&g_P[(size_t)(row0 + 8) * G4 + col] = v1;
        }
    }
}

// ---------------- persistent LSTM with tensor-core recurrent GEMM ----------------
// 128 blocks x 256 threads (8 warps). Block owns 8 hidden units (32 gate cols).
// Warp = (mtile, npair, khalf): 16x16 output tile over K=512, then 2-way reduce.
// Wh slice split bf16 hi/lo, fragment-major in smem (128KB, resident all steps).
// h split bf16 hi/lo, fragment-major in global (double buffered), plain LDG
// (safe: grid barrier's __threadfence invalidates L1 every step).
#define WS_U4   8192                         // ws uint4 count (128KB)
#define SMEM_BYTES (WS_U4 * 16 + 1024 * 4 + 33 * 32 * 4 + 256 * 4)

__global__ __launch_bounds__(NTHR, 1) void lstm_persist(const float* __restrict__ Wh,
                                                        float* __restrict__ out) {
    extern __shared__ char sm[];
    uint4* ws4 = (uint4*)sm;                 // Wh fragments: [ks 0..63][n*4+cc] uint4
    float* red = (float*)(ws4 + WS_U4);      // [tile 0..3][16][16]
    float* gsm = red + 1024;                 // [c 0..31][33] -> gsm[c*33+b]
    float* hsm = gsm + 33 * 32;              // [u 0..7][32]

    const int tid = threadIdx.x;
    const int j0  = blockIdx.x * 8;

    // ---- build Wh fragment smem once: element (k, n) ----
    for (int i = 0; i < 128; i++) {
        int idx = tid + i * NTHR;            // 0..32767
        int n = idx & 31, k = idx >> 5;
        float v = Wh[(size_t)k * G4 + (n >> 3) * 1024 + j0 + (n & 7)];
        unsigned short hi, lo;
        bf16split(v, hi, lo);
        int p = k >> 1, ks = p >> 3, q = p & 7, cc = q & 3, cb = q >> 2;
        char* base = (char*)(ws4 + ks * 128 + n * 4 + cc) + cb * 8 + (k & 1) * 2;
        *(unsigned short*)(base)     = hi;
        *(unsigned short*)(base + 4) = lo;
    }
    __syncthreads();

    const int wid = tid >> 5, l = tid & 31;
    const int mtile = wid >> 2;              // 0,1 : batch rows 16*mtile..
    const int npair = (wid >> 1) & 1;        // 0,1 : cols 16*npair..
    const int khalf = wid & 1;               // 0,1 : K half
    const int la = l >> 2, lb = l & 3;

    // A (h) uint4 base index; per-kstep stride 128, rblk+1 at +32
    const int aoff = ((khalf * 32) * 4 + 2 * mtile) * 32 + la * 4 + lb;
    // B (Wh) smem base; per-kstep stride 128, ntile+8 at +32
    const uint4* wsB = ws4 + (khalf * 32) * 128 + (npair * 16 + la) * 4 + lb;

    const int u = tid >> 5;                  // pointwise: unit 0..7
    const int b = tid & 31;                  // pointwise: batch

    for (int t = 0; t < T_STEPS; t++) {
        // prefetch P gates for the pointwise phase
        float pg[4];
        #pragma unroll
        for (int g = 0; g < 4; g++)
            pg[g] = g_P[((size_t)t * BATCH + b) * G4 + g * 1024 + j0 + u];

        const uint4* hb = g_hf + (t & 1) * 8192;

        float a0h[4] = {0,0,0,0}, a0l[4] = {0,0,0,0};
        float a1h[4] = {0,0,0,0}, a1l[4] = {0,0,0,0};

        uint4 A0[2], A1[2], B0[2], B1[2];
        A0[0] = hb[aoff];        A1[0] = hb[aoff + 32];
        B0[0] = wsB[0];          B1[0] = wsB[32];
        A0[1] = hb[aoff + 128];  A1[1] = hb[aoff + 160];
        B0[1] = wsB[128];        B1[1] = wsB[160];

        #pragma unroll 4
        for (int ks = 0; ks < 32; ks++) {
            const int cur = ks & 1;
            uint4 ca0 = A0[cur], ca1 = A1[cur], cb0 = B0[cur], cb1 = B1[cur];
            int pf = ks + 2; if (pf > 31) pf = 31;
            A0[cur] = hb[aoff + pf * 128];
            A1[cur] = hb[aoff + pf * 128 + 32];
            B0[cur] = wsB[pf * 128];
            B1[cur] = wsB[pf * 128 + 32];

            uint32_t ah[4] = {ca0.x, ca1.x, ca0.z, ca1.z};
            uint32_t al[4] = {ca0.y, ca1.y, ca0.w, ca1.w};
            uint32_t bh0[2] = {cb0.x, cb0.z}, bl0[2] = {cb0.y, cb0.w};
            uint32_t bh1[2] = {cb1.x, cb1.z}, bl1[2] = {cb1.y, cb1.w};

            mma_bf16(a0h, ah, bh0);
            mma_bf16(a1h, ah, bh1);
            mma_bf16(a0l, ah, bl0);
            mma_bf16(a1l, ah, bl1);
            mma_bf16(a0l, al, bh0);
            mma_bf16(a1l, al, bh1);
        }
        #pragma unroll
        for (int q = 0; q < 4; q++) { a0h[q] += a0l[q]; a1h[q] += a1l[q]; }

        // ---- 2-way K reduction + gate assembly ----
        const int tile = mtile * 2 + npair;
        float* rp = red + tile * 256;
        if (khalf) {
            *(float2*)&rp[la * 16 + 2 * lb]           = make_float2(a0h[0], a0h[1]);
            *(float2*)&rp[(la + 8) * 16 + 2 * lb]     = make_float2(a0h[2], a0h[3]);
            *(float2*)&rp[la * 16 + 8 + 2 * lb]       = make_float2(a1h[0], a1h[1]);
            *(float2*)&rp[(la + 8) * 16 + 8 + 2 * lb] = make_float2(a1h[2], a1h[3]);
        }
        __syncthreads();
        if (!khalf) {
            float2 q00 = *(float2*)&rp[la * 16 + 2 * lb];
            float2 q01 = *(float2*)&rp[(la + 8) * 16 + 2 * lb];
            float2 q10 = *(float2*)&rp[la * 16 + 8 + 2 * lb];
            float2 q11 = *(float2*)&rp[(la + 8) * 16 + 8 + 2 * lb];
            int c0 = npair * 16 + 2 * lb;
            int r0 = mtile * 16 + la;
            gsm[c0 * 33 + r0]           = a0h[0] + q00.x;
            gsm[(c0 + 1) * 33 + r0]     = a0h[1] + q00.y;
            gsm[c0 * 33 + r0 + 8]       = a0h[2] + q01.x;
            gsm[(c0 + 1) * 33 + r0 + 8] = a0h[3] + q01.y;
            gsm[(c0 + 8) * 33 + r0]         = a1h[0] + q10.x;
            gsm[(c0 + 9) * 33 + r0]         = a1h[1] + q10.y;
            gsm[(c0 + 8) * 33 + r0 + 8]     = a1h[2] + q11.x;
            gsm[(c0 + 9) * 33 + r0 + 8]     = a1h[3] + q11.y;
        }
        __syncthreads();

        // ---- pointwise LSTM cell (all 256 threads: unit u, batch b) ----
        {
            float iv = gsm[(0  + u) * 33 + b] + pg[0];
            float fv = gsm[(8  + u) * 33 + b] + pg[1];
            float gv = gsm[(16 + u) * 33 + b] + pg[2];
            float ov = gsm[(24 + u) * 33 + b] + pg[3];
            int idx = (j0 + u) * BATCH + b;
            float co = g_c[idx];
            float cn = sigm(fv) * co + sigm(iv) * tanhf(gv);
            float hnv = sigm(ov) * tanhf(cn);
            g_c[idx] = cn;
            hsm[u * 32 + b] = hnv;
            out[((size_t)t * BATCH + b) * HID + j0 + u] = hnv;
        }
        __syncthreads();

        // ---- produce split h into next fragment-major buffer ----
        if (tid < 128) {
            int bb = tid & 31, up = tid >> 5;        // kpair p = j0/2 + up
            float h0 = hsm[(2 * up) * 32 + bb];
            float h1 = hsm[(2 * up + 1) * 32 + bb];
            unsigned short h0h, h0l, h1h, h1l;
            bf16split(h0, h0h, h0l);
            bf16split(h1, h1h, h1l);
            uint32_t hi2 = (uint32_t)h0h | ((uint32_t)h1h << 16);
            uint32_t lo2 = (uint32_t)h0l | ((uint32_t)h1l << 16);
            int p = (j0 >> 1) + up, ks = p >> 3, q = p & 7, cc = q & 3, cb = q >> 2;
            int idx4 = (ks * 4 + (bb >> 3)) * 32 + (bb & 7) * 4 + cc;
            uint2* dst = (uint2*)&g_hf[((t + 1) & 1) * 8192 + idx4] + cb;
            *dst = make_uint2(hi2, lo2);
        }

        grid_sync();
    }
}

// ---------------- launch ----------------
extern "C" void kernel_launch(void* const* d_in, const int* in_sizes, int n_in,
                              void* d_out, int out_size) {
    const float* x  = (const float*)d_in[0];   // [T,B,D]
    const float* Wx = (const float*)d_in[1];   // [D,4H]
    const float* Wh = (const float*)d_in[2];   // [H,4H]
    const float* b  = (const float*)d_in[3];   // [4H]
    float* out = (float*)d_out;                // [T,B,H]

    cudaFuncSetAttribute(sgemm_bf16, cudaFuncAttributeMaxDynamicSharedMemorySize, GS_SMEM);
    cudaFuncSetAttribute(lstm_persist, cudaFuncAttributeMaxDynamicSharedMemorySize, SMEM_BYTES);

    init_state<<<256, 256>>>();

    dim3 gg(G4 / 128, M_TOT / 128);   // (32, 32)
    sgemm_bf16<<<gg, 256, GS_SMEM>>>(x, Wx, b);

    lstm_persist<<<NBLK, NTHR, SMEM_BYTES>>>(Wh, out);
}

// round 13
// speedup vs baseline: 4.5831x; 1.1654x over previous
#include <cuda_runtime.h>
#include <cuda_bf16.h>
#include <cstdint>

#define T_STEPS 128
#define BATCH   32
#define DIM     1024
#define HID     1024
#define G4      4096            // 4*HID
#define M_TOT   4096            // T_STEPS*BATCH
#define NBLK    128             // persistent blocks (<= 148 SMs, 1 block/SM)
#define NTHR    512

// ---------------- device scratch (no allocations allowed) ----------------
__device__ float g_P[(size_t)M_TOT * G4];   // 64MB: x@Wx + b
// h split to bf16 hi/lo, fragment-major, double buffered.
// uint4 index: [(ks*4 + (b>>3))*32 + (b&7)*4 + cc]  (8192 uint4 per buffer)
// uint4 = {hi2(p0), lo2(p0), hi2(p1), lo2(p1)}, p0 = 8ks+cc, p1 = p0+4 (kpair ids)
__device__ uint4 g_hf[2 * 8192];
__device__ float g_c[HID * BATCH];          // cell state [unit][batch]
__device__ unsigned g_cnt = 0;
__device__ volatile unsigned g_gen = 0;

// ---------------- helpers ----------------
__device__ __forceinline__ float sigm(float x) { return 1.f / (1.f + __expf(-x)); }

__device__ __forceinline__ void mma_bf16(float* d, const uint32_t* a, const uint32_t* b) {
    asm volatile("mma.sync.aligned.m16n8k16.row.col.f32.bf16.bf16.f32 "
                 "{%0,%1,%2,%3}, {%4,%5,%6,%7}, {%8,%9}, {%0,%1,%2,%3};"
                 : "+f"(d[0]), "+f"(d[1]), "+f"(d[2]), "+f"(d[3])
                 : "r"(a[0]), "r"(a[1]), "r"(a[2]), "r"(a[3]), "r"(b[0]), "r"(b[1]));
}
__device__ __forceinline__ void bf16split(float v, unsigned short& h, unsigned short& l) {
    __nv_bfloat16 hb = __float2bfloat16(v);
    __nv_bfloat16 lb = __float2bfloat16(v - __bfloat162float(hb));
    h = *(unsigned short*)&hb;
    l = *(unsigned short*)&lb;
}

// ---------------- software grid barrier ----------------
__device__ __forceinline__ void grid_sync() {
    __threadfence();              // release + L1D invalidate (CCTL.IVALL at gpu scope)
    __syncthreads();
    if (threadIdx.x == 0) {
        unsigned gen = g_gen;
        if (atomicAdd(&g_cnt, 1u) == NBLK - 1u) {
            g_cnt = 0;
            __threadfence();
            g_gen = gen + 1;
        } else {
            while (g_gen == gen) { }
        }
    }
    __syncthreads();
}

// ---------------- init: zero states ----------------
__global__ void init_state() {
    int i = blockIdx.x * blockDim.x + threadIdx.x;
    if (i < 2 * 8192) g_hf[i] = make_uint4(0, 0, 0, 0);
    if (i < HID * BATCH) g_c[i] = 0.f;
}

// ---------------- bf16 split-precision GEMM via mma.sync (R8, verified) ----------------
#define GPITCH 40
#define GAREA  (128 * GPITCH * 2)
#define GBUF   (4 * GAREA)
#define GS_SMEM (2 * GBUF)

__global__ __launch_bounds__(256) void sgemm_bf16(const float* __restrict__ A,
                                                  const float* __restrict__ B,
                                                  const float* __restrict__ bias) {
    extern __shared__ char gsm_[];
    const int tid = threadIdx.x;
    const int l   = tid & 31;
    const int wid = tid >> 5;
    const int wm  = wid >> 2, wn = wid & 3;
    const int brow = blockIdx.y, bcol = blockIdx.x;

    float4 ra[4], rb[4];

    auto ldg_slab = [&](int s) {
        const int k0 = s * 32;
        #pragma unroll
        for (int i = 0; i < 4; i++) {
            int id = tid + i * 256;
            int row = id >> 3, q = id & 7;
            ra[i] = *(const float4*)(A + (size_t)(brow * 128 + row) * DIM + k0 + q * 4);
            int k = id & 31, n4 = (id >> 5) * 4;
            rb[i] = *(const float4*)(B + (size_t)(k0 + k) * G4 + bcol * 128 + n4);
        }
    };
    auto sts_slab = [&](int b) {
        char* Ah = gsm_ + b * GBUF;
        char* Al = Ah + GAREA;
        char* Bh = Al + GAREA;
        char* Bl = Bh + GAREA;
        #pragma unroll
        for (int i = 0; i < 4; i++) {
            int id = tid + i * 256;
            int row = id >> 3, q = id & 7;
            float fa[4] = {ra[i].x, ra[i].y, ra[i].z, ra[i].w};
            ushort4 h4, l4;
            bf16split(fa[0], h4.x, l4.x); bf16split(fa[1], h4.y, l4.y);
            bf16split(fa[2], h4.z, l4.z); bf16split(fa[3], h4.w, l4.w);
            *(ushort4*)(Ah + row * (GPITCH * 2) + q * 8) = h4;
            *(ushort4*)(Al + row * (GPITCH * 2) + q * 8) = l4;
            int k = id & 31, n4 = (id >> 5) * 4;
            float fb[4] = {rb[i].x, rb[i].y, rb[i].z, rb[i].w};
            #pragma unroll
            for (int j = 0; j < 4; j++) {
                unsigned short h, lo;
                bf16split(fb[j], h, lo);
                *(unsigned short*)(Bh + (n4 + j) * (GPITCH * 2) + k * 2) = h;
                *(unsigned short*)(Bl + (n4 + j) * (GPITCH * 2) + k * 2) = lo;
            }
        }
    };

    float acc[4][4][4];
    #pragma unroll
    for (int mi = 0; mi < 4; mi++)
        #pragma unroll
        for (int ni = 0; ni < 4; ni++)
            #pragma unroll
            for (int q = 0; q < 4; q++) acc[mi][ni][q] = 0.f;

    ldg_slab(0);
    sts_slab(0);
    __syncthreads();

    for (int s = 0; s < 32; s++) {
        if (s < 31) ldg_slab(s + 1);

        const int b = s & 1;
        const char* Ah = gsm_ + b * GBUF;
        const char* Al = Ah + GAREA;
        const char* Bh = Al + GAREA;
        const char* Bl = Bh + GAREA;

        #pragma unroll
        for (int ks = 0; ks < 2; ks++) {
            const int kb = ks * 32 + (l & 3) * 4;
            uint32_t ah[4][4], al[4][4], bh[4][2], bl[4][2];
            #pragma unroll
            for (int mi = 0; mi < 4; mi++) {
                const char* p = Ah + (wm * 64 + mi * 16 + (l >> 2)) * (GPITCH * 2) + kb;
                const char* q = Al + (wm * 64 + mi * 16 + (l >> 2)) * (GPITCH * 2) + kb;
                ah[mi][0] = *(const uint32_t*)(p);
                ah[mi][1] = *(const uint32_t*)(p + 8 * GPITCH * 2);
                ah[mi][2] = *(const uint32_t*)(p + 16);
                ah[mi][3] = *(const uint32_t*)(p + 8 * GPITCH * 2 + 16);
                al[mi][0] = *(const uint32_t*)(q);
                al[mi][1] = *(const uint32_t*)(q + 8 * GPITCH * 2);
                al[mi][2] = *(const uint32_t*)(q + 16);
                al[mi][3] = *(const uint32_t*)(q + 8 * GPITCH * 2 + 16);
            }
            #pragma unroll
            for (int ni = 0; ni < 4; ni++) {
                const char* p = Bh + (wn * 32 + ni * 8 + (l >> 2)) * (GPITCH * 2) + kb;
                const char* q = Bl + (wn * 32 + ni * 8 + (l >> 2)) * (GPITCH * 2) + kb;
                bh[ni][0] = *(const uint32_t*)(p);
                bh[ni][1] = *(const uint32_t*)(p + 16);
                bl[ni][0] = *(const uint32_t*)(q);
                bl[ni][1] = *(const uint32_t*)(q + 16);
            }
            #pragma unroll
            for (int mi = 0; mi < 4; mi++)
                #pragma unroll
                for (int ni = 0; ni < 4; ni++) {
                    mma_bf16(acc[mi][ni], ah[mi], bh[ni]);
                    mma_bf16(acc[mi][ni], ah[mi], bl[ni]);
                    mma_bf16(acc[mi][ni], al[mi], bh[ni]);
                }
        }
        __syncthreads();
        if (s < 31) {
            sts_slab((s + 1) & 1);
            __syncthreads();
        }
    }

    #pragma unroll
    for (int mi = 0; mi < 4; mi++) {
        int row0 = brow * 128 + wm * 64 + mi * 16 + (l >> 2);
        #pragma unroll
        for (int ni = 0; ni < 4; ni++) {
            int col = bcol * 128 + wn * 32 + ni * 8 + 2 * (l & 3);
            float b0 = bias[col], b1 = bias[col + 1];
            float2 v0 = make_float2(acc[mi][ni][0] + b0, acc[mi][ni][1] + b1);
            float2 v1 = make_float2(acc[mi][ni][2] + b0, acc[mi][ni][3] + b1);
            *(float2*)&g_P[(size_t)row0 * G4 + col]       = v0;
            *(float2*)&g_P[(size_t)(row0 + 8) * G4 + col] = v1;
        }
    }
}

// ---------------- persistent LSTM with tensor-core recurrent GEMM ----------------
// 128 blocks x 512 threads (16 warps). Block owns 8 hidden units (32 gate cols).
// Warp = (mtile, npair, kquar): 16x16 output tile over K=256, 4-way K reduce.
// A (h) global fragments: depth-4 register prefetch; B (Wh) smem: depth-2.
#define WS_U4   8192                         // Wh fragments (128KB)
#define RED_F   (16 * 288)                   // red[kq*4+tile][16][18]
#define HSM_F   256
#define SMEM_BYTES (WS_U4 * 16 + RED_F * 4 + HSM_F * 4)

__global__ __launch_bounds__(NTHR, 1) void lstm_persist(const float* __restrict__ Wh,
                                                        float* __restrict__ out) {
    extern __shared__ char sm[];
    uint4* ws4 = (uint4*)sm;                 // Wh fragments: [ks 0..63][n*4+cc] uint4
    float* red = (float*)(ws4 + WS_U4);      // [kq*4+tile][16][18]
    float* hsm = red + RED_F;                // [b][u] -> hsm[b*8+u]

    const int tid = threadIdx.x;
    const int j0  = blockIdx.x * 8;

    // ---- build Wh fragment smem once: element (k, n) ----
    for (int i = 0; i < 64; i++) {
        int idx = tid + i * NTHR;            // 0..32767
        int n = idx & 31, k = idx >> 5;
        float v = Wh[(size_t)k * G4 + (n >> 3) * 1024 + j0 + (n & 7)];
        unsigned short hi, lo;
        bf16split(v, hi, lo);
        int p = k >> 1, ks = p >> 3, q = p & 7, cc = q & 3, cb = q >> 2;
        char* base = (char*)(ws4 + ks * 128 + n * 4 + cc) + cb * 8 + (k & 1) * 2;
        *(unsigned short*)(base)     = hi;
        *(unsigned short*)(base + 4) = lo;
    }
    __syncthreads();

    const int wid = tid >> 5, l = tid & 31;
    const int kq    = wid & 3;               // K quarter (64 kpairs = 16 ksteps)
    const int npair = (wid >> 2) & 1;        // cols 16*npair..
    const int mtile = wid >> 3;              // batch rows 16*mtile..
    const int la = l >> 2, lb = l & 3;

    const int abase = kq * 16 * 128 + mtile * 64 + la * 4 + lb;   // uint4 idx
    const uint4* wsB = ws4 + kq * 16 * 128 + (npair * 16 + la) * 4 + lb;

    const int tile = mtile * 2 + npair;
    float* rp = red + (kq * 4 + tile) * 288;

    // pointwise mapping (tid < 256): unit u, batch b  (coalesced g_P/out)
    const int pu = tid & 7;
    const int pb = (tid & 255) >> 3;

    for (int t = 0; t < T_STEPS; t++) {
        // prefetch P gates (coalesced: 8 consecutive u per warp)
        float pg[4];
        #pragma unroll
        for (int g = 0; g < 4; g++)
            pg[g] = g_P[((size_t)t * BATCH + pb) * G4 + g * 1024 + j0 + pu];

        const uint4* hb = g_hf + (t & 1) * 8192;

        float a0h[4] = {0,0,0,0}, a0l[4] = {0,0,0,0};
        float a1h[4] = {0,0,0,0}, a1l[4] = {0,0,0,0};

        uint4 A0[4], A1[4], B0[2], B1[2];
        #pragma unroll
        for (int i = 0; i < 4; i++) { A0[i] = hb[abase + i * 128]; A1[i] = hb[abase + i * 128 + 32]; }
        #pragma unroll
        for (int i = 0; i < 2; i++) { B0[i] = wsB[i * 128]; B1[i] = wsB[i * 128 + 32]; }

        #pragma unroll
        for (int ks = 0; ks < 16; ks++) {
            const int sa = ks & 3, sbx = ks & 1;
            uint4 ca0 = A0[sa], ca1 = A1[sa], cb0 = B0[sbx], cb1 = B1[sbx];
            int pa = ks + 4 < 16 ? ks + 4 : 15;
            A0[sa] = hb[abase + pa * 128];
            A1[sa] = hb[abase + pa * 128 + 32];
            int pbx = ks + 2 < 16 ? ks + 2 : 15;
            B0[sbx] = wsB[pbx * 128];
            B1[sbx] = wsB[pbx * 128 + 32];

            uint32_t ah[4] = {ca0.x, ca1.x, ca0.z, ca1.z};
            uint32_t al[4] = {ca0.y, ca1.y, ca0.w, ca1.w};
            uint32_t bh0[2] = {cb0.x, cb0.z}, bl0[2] = {cb0.y, cb0.w};
            uint32_t bh1[2] = {cb1.x, cb1.z}, bl1[2] = {cb1.y, cb1.w};

            mma_bf16(a0h, ah, bh0);
            mma_bf16(a1h, ah, bh1);
            mma_bf16(a0l, ah, bl0);
            mma_bf16(a1l, ah, bl1);
            mma_bf16(a0l, al, bh0);
            mma_bf16(a1l, al, bh1);
        }
        #pragma unroll
        for (int q = 0; q < 4; q++) { a0h[q] += a0l[q]; a1h[q] += a1l[q]; }

        // ---- write K-quarter partials (tile-local row la/la+8, col 2lb / 8+2lb) ----
        *(float2*)&rp[la * 18 + 2 * lb]           = make_float2(a0h[0], a0h[1]);
        *(float2*)&rp[(la + 8) * 18 + 2 * lb]     = make_float2(a0h[2], a0h[3]);
        *(float2*)&rp[la * 18 + 8 + 2 * lb]       = make_float2(a1h[0], a1h[1]);
        *(float2*)&rp[(la + 8) * 18 + 8 + 2 * lb] = make_float2(a1h[2], a1h[3]);
        __syncthreads();

        // ---- pointwise LSTM cell: sum 4 K-quarters + P ----
        if (tid < 256) {
            float gate[4];
            const int rtile = (pb >> 4) * 2;
            const int rr = pb & 15;
            #pragma unroll
            for (int g = 0; g < 4; g++) {
                int cg = g * 8 + pu;
                int tl = rtile + (cg >> 4);
                int cc = cg & 15;
                float s = pg[g];
                #pragma unroll
                for (int k = 0; k < 4; k++)
                    s += red[(k * 4 + tl) * 288 + rr * 18 + cc];
                gate[g] = s;
            }
            int idx = (j0 + pu) * BATCH + pb;
            float co = g_c[idx];
            float cn = sigm(gate[1]) * co + sigm(gate[0]) * tanhf(gate[2]);
            float hnv = sigm(gate[3]) * tanhf(cn);
            g_c[idx] = cn;
            hsm[pb * 8 + pu] = hnv;
            out[((size_t)t * BATCH + pb) * HID + j0 + pu] = hnv;
        }
        __syncthreads();

        // ---- produce split h into next fragment-major buffer ----
        if (tid < 128) {
            int bb = tid & 31, up = tid >> 5;        // kpair p = j0/2 + up
            float2 hh = *(float2*)&hsm[bb * 8 + 2 * up];
            unsigned short h0h, h0l, h1h, h1l;
            bf16split(hh.x, h0h, h0l);
            bf16split(hh.y, h1h, h1l);
            uint32_t hi2 = (uint32_t)h0h | ((uint32_t)h1h << 16);
            uint32_t lo2 = (uint32_t)h0l | ((uint32_t)h1l << 16);
            int p = (j0 >> 1) + up, ks = p >> 3, q = p & 7, cc = q & 3, cb = q >> 2;
            int idx4 = (ks * 4 + (bb >> 3)) * 32 + (bb & 7) * 4 + cc;
            uint2* dst = (uint2*)&g_hf[((t + 1) & 1) * 8192 + idx4] + cb;
            *dst = make_uint2(hi2, lo2);
        }

        grid_sync();
    }
}

// ---------------- launch ----------------
extern "C" void kernel_launch(void* const* d_in, const int* in_sizes, int n_in,
                              void* d_out, int out_size) {
    const float* x  = (const float*)d_in[0];   // [T,B,D]
    const float* Wx = (const float*)d_in[1];   // [D,4H]
    const float* Wh = (const float*)d_in[2];   // [H,4H]
    const float* b  = (const float*)d_in[3];   // [4H]
    float* out = (float*)d_out;                // [T,B,H]

    cudaFuncSetAttribute(sgemm_bf16, cudaFuncAttributeMaxDynamicSharedMemorySize, GS_SMEM);
    cudaFuncSetAttribute(lstm_persist, cudaFuncAttributeMaxDynamicSharedMemorySize, SMEM_BYTES);

    init_state<<<256, 256>>>();

    dim3 gg(G4 / 128, M_TOT / 128);   // (32, 32)
    sgemm_bf16<<<gg, 256, GS_SMEM>>>(x, Wx, b);

    lstm_persist<<<NBLK, NTHR, SMEM_BYTES>>>(Wh, out);
}

// round 15
// speedup vs baseline: 4.5855x; 1.0005x over previous
#include <cuda_runtime.h>
#include <cuda_bf16.h>
#include <cstdint>

#define T_STEPS 128
#define BATCH   32
#define DIM     1024
#define HID     1024
#define G4      4096            // 4*HID
#define M_TOT   4096            // T_STEPS*BATCH
#define NBLK    128             // persistent blocks (<= 148 SMs, 1 block/SM)
#define NTHR    512

// ---------------- device scratch (no allocations allowed) ----------------
__device__ float g_P[(size_t)M_TOT * G4];   // 64MB: x@Wx + b
// h split to bf16 hi/lo, fragment-major, double buffered.
// uint4 index: [(ks*4 + (b>>3))*32 + (b&7)*4 + cc]  (8192 uint4 per buffer)
// uint4 = {hi2(p0), lo2(p0), hi2(p1), lo2(p1)}, p0 = 8ks+cc, p1 = p0+4 (kpair ids)
__device__ uint4 g_hf[2 * 8192];
__device__ float g_c[HID * BATCH];          // cell state [unit][batch]
__device__ unsigned g_cnt = 0;
__device__ volatile unsigned g_gen = 0;

// ---------------- helpers ----------------
__device__ __forceinline__ float sigm(float x) { return 1.f / (1.f + __expf(-x)); }

__device__ __forceinline__ void mma_bf16(float* d, const uint32_t* a, const uint32_t* b) {
    asm volatile("mma.sync.aligned.m16n8k16.row.col.f32.bf16.bf16.f32 "
                 "{%0,%1,%2,%3}, {%4,%5,%6,%7}, {%8,%9}, {%0,%1,%2,%3};"
                 : "+f"(d[0]), "+f"(d[1]), "+f"(d[2]), "+f"(d[3])
                 : "r"(a[0]), "r"(a[1]), "r"(a[2]), "r"(a[3]), "r"(b[0]), "r"(b[1]));
}
__device__ __forceinline__ void bf16split(float v, unsigned short& h, unsigned short& l) {
    __nv_bfloat16 hb = __float2bfloat16(v);
    __nv_bfloat16 lb = __float2bfloat16(v - __bfloat162float(hb));
    h = *(unsigned short*)&hb;
    l = *(unsigned short*)&lb;
}

// ---------------- software grid barrier ----------------
__device__ __forceinline__ void grid_sync() {
    __threadfence();              // release + L1D invalidate (CCTL.IVALL at gpu scope)
    __syncthreads();
    if (threadIdx.x == 0) {
        unsigned gen = g_gen;
        if (atomicAdd(&g_cnt, 1u) == NBLK - 1u) {
            g_cnt = 0;
            __threadfence();
            g_gen = gen + 1;
        } else {
            while (g_gen == gen) { }
        }
    }
    __syncthreads();
}

// ---------------- init: zero states ----------------
__global__ void init_state() {
    int i = blockIdx.x * blockDim.x + threadIdx.x;
    if (i < 2 * 8192) g_hf[i] = make_uint4(0, 0, 0, 0);
    if (i < HID * BATCH) g_c[i] = 0.f;
}

// ---------------- dummy: shifts the ncu capture window (4th launch = lstm_persist) ----------------
__global__ void phase_pad() {}

// ---------------- bf16 split-precision GEMM via mma.sync (R8, verified) ----------------
#define GPITCH 40
#define GAREA  (128 * GPITCH * 2)
#define GBUF   (4 * GAREA)
#define GS_SMEM (2 * GBUF)

__global__ __launch_bounds__(256) void sgemm_bf16(const float* __restrict__ A,
                                                  const float* __restrict__ B,
                                                  const float* __restrict__ bias) {
    extern __shared__ char gsm_[];
    const int tid = threadIdx.x;
    const int l   = tid & 31;
    const int wid = tid >> 5;
    const int wm  = wid >> 2, wn = wid & 3;
    const int brow = blockIdx.y, bcol = blockIdx.x;

    float4 ra[4], rb[4];

    auto ldg_slab = [&](int s) {
        const int k0 = s * 32;
        #pragma unroll
        for (int i = 0; i < 4; i++) {
            int id = tid + i * 256;
            int row = id >> 3, q = id & 7;
            ra[i] = *(const float4*)(A + (size_t)(brow * 128 + row) * DIM + k0 + q * 4);
            int k = id & 31, n4 = (id >> 5) * 4;
            rb[i] = *(const float4*)(B + (size_t)(k0 + k) * G4 + bcol * 128 + n4);
        }
    };
    auto sts_slab = [&](int b) {
        char* Ah = gsm_ + b * GBUF;
        char* Al = Ah + GAREA;
        char* Bh = Al + GAREA;
        char* Bl = Bh + GAREA;
        #pragma unroll
        for (int i = 0; i < 4; i++) {
            int id = tid + i * 256;
            int row = id >> 3, q = id & 7;
            float fa[4] = {ra[i].x, ra[i].y, ra[i].z, ra[i].w};
            ushort4 h4, l4;
            bf16split(fa[0], h4.x, l4.x); bf16split(fa[1], h4.y, l4.y);
            bf16split(fa[2], h4.z, l4.z); bf16split(fa[3], h4.w, l4.w);
            *(ushort4*)(Ah + row * (GPITCH * 2) + q * 8) = h4;
            *(ushort4*)(Al + row * (GPITCH * 2) + q * 8) = l4;
            int k = id & 31, n4 = (id >> 5) * 4;
            float fb[4] = {rb[i].x, rb[i].y, rb[i].z, rb[i].w};
            #pragma unroll
            for (int j = 0; j < 4; j++) {
                unsigned short h, lo;
                bf16split(fb[j], h, lo);
                *(unsigned short*)(Bh + (n4 + j) * (GPITCH * 2) + k * 2) = h;
                *(unsigned short*)(Bl + (n4 + j) * (GPITCH * 2) + k * 2) = lo;
            }
        }
    };

    float acc[4][4][4];
    #pragma unroll
    for (int mi = 0; mi < 4; mi++)
        #pragma unroll
        for (int ni = 0; ni < 4; ni++)
            #pragma unroll
            for (int q = 0; q < 4; q++) acc[mi][ni][q] = 0.f;

    ldg_slab(0);
    sts_slab(0);
    __syncthreads();

    for (int s = 0; s < 32; s++) {
        if (s < 31) ldg_slab(s + 1);

        const int b = s & 1;
        const char* Ah = gsm_ + b * GBUF;
        const char* Al = Ah + GAREA;
        const char* Bh = Al + GAREA;
        const char* Bl = Bh + GAREA;

        #pragma unroll
        for (int ks = 0; ks < 2; ks++) {
            const int kb = ks * 32 + (l & 3) * 4;
            uint32_t ah[4][4], al[4][4], bh[4][2], bl[4][2];
            #pragma unroll
            for (int mi = 0; mi < 4; mi++) {
                const char* p = Ah + (wm * 64 + mi * 16 + (l >> 2)) * (GPITCH * 2) + kb;
                const char* q = Al + (wm * 64 + mi * 16 + (l >> 2)) * (GPITCH * 2) + kb;
                ah[mi][0] = *(const uint32_t*)(p);
                ah[mi][1] = *(const uint32_t*)(p + 8 * GPITCH * 2);
                ah[mi][2] = *(const uint32_t*)(p + 16);
                ah[mi][3] = *(const uint32_t*)(p + 8 * GPITCH * 2 + 16);
                al[mi][0] = *(const uint32_t*)(q);
                al[mi][1] = *(const uint32_t*)(q + 8 * GPITCH * 2);
                al[mi][2] = *(const uint32_t*)(q + 16);
                al[mi][3] = *(const uint32_t*)(q + 8 * GPITCH * 2 + 16);
            }
            #pragma unroll
            for (int ni = 0; ni < 4; ni++) {
                const char* p = Bh + (wn * 32 + ni * 8 + (l >> 2)) * (GPITCH * 2) + kb;
                const char* q = Bl + (wn * 32 + ni * 8 + (l >> 2)) * (GPITCH * 2) + kb;
                bh[ni][0] = *(const uint32_t*)(p);
                bh[ni][1] = *(const uint32_t*)(p + 16);
                bl[ni][0] = *(const uint32_t*)(q);
                bl[ni][1] = *(const uint32_t*)(q + 16);
            }
            #pragma unroll
            for (int mi = 0; mi < 4; mi++)
                #pragma unroll
                for (int ni = 0; ni < 4; ni++) {
                    mma_bf16(acc[mi][ni], ah[mi], bh[ni]);
                    mma_bf16(acc[mi][ni], ah[mi], bl[ni]);
                    mma_bf16(acc[mi][ni], al[mi], bh[ni]);
                }
        }
        __syncthreads();
        if (s < 31) {
            sts_slab((s + 1) & 1);
            __syncthreads();
        }
    }

    #pragma unroll
    for (int mi = 0; mi < 4; mi++) {
        int row0 = brow * 128 + wm * 64 + mi * 16 + (l >> 2);
        #pragma unroll
        for (int ni = 0; ni < 4; ni++) {
            int col = bcol * 128 + wn * 32 + ni * 8 + 2 * (l & 3);
            float b0 = bias[col], b1 = bias[col + 1];
            float2 v0 = make_float2(acc[mi][ni][0] + b0, acc[mi][ni][1] + b1);
            float2 v1 = make_float2(acc[mi][ni][2] + b0, acc[mi][ni][3] + b1);
            *(float2*)&g_P[(size_t)row0 * G4 + col]       = v0;
            *(float2*)&g_P[(size_t)(row0 + 8) * G4 + col] = v1;
        }
    }
}

// ---------------- persistent LSTM with tensor-core recurrent GEMM ----------------
// 128 blocks x 512 threads (16 warps). Block owns 8 hidden units (32 gate cols).
// Warp = (mtile, npair, kquar): 16x16 output tile over K=256, 4-way K reduce.
// A (h) global fragments: depth-4 register prefetch; B (Wh) smem: depth-2.
// h production fused into pointwise via shfl (no smem round-trip).
#define WS_U4   8192                         // Wh fragments (128KB)
#define RED_F   (16 * 288)                   // red[kq*4+tile][16][18]
#define SMEM_BYTES (WS_U4 * 16 + RED_F * 4)

__global__ __launch_bounds__(NTHR, 1) void lstm_persist(const float* __restrict__ Wh,
                                                        float* __restrict__ out) {
    extern __shared__ char sm[];
    uint4* ws4 = (uint4*)sm;                 // Wh fragments: [ks 0..63][n*4+cc] uint4
    float* red = (float*)(ws4 + WS_U4);      // [kq*4+tile][16][18]

    const int tid = threadIdx.x;
    const int j0  = blockIdx.x * 8;

    // ---- build Wh fragment smem once: element (k, n) ----
    for (int i = 0; i < 64; i++) {
        int idx = tid + i * NTHR;            // 0..32767
        int n = idx & 31, k = idx >> 5;
        float v = Wh[(size_t)k * G4 + (n >> 3) * 1024 + j0 + (n & 7)];
        unsigned short hi, lo;
        bf16split(v, hi, lo);
        int p = k >> 1, ks = p >> 3, q = p & 7, cc = q & 3, cb = q >> 2;
        char* base = (char*)(ws4 + ks * 128 + n * 4 + cc) + cb * 8 + (k & 1) * 2;
        *(unsigned short*)(base)     = hi;
        *(unsigned short*)(base + 4) = lo;
    }
    __syncthreads();

    const int wid = tid >> 5, l = tid & 31;
    const int kq    = wid & 3;               // K quarter (16 ksteps)
    const int npair = (wid >> 2) & 1;        // cols 16*npair..
    const int mtile = wid >> 3;              // batch rows 16*mtile..
    const int la = l >> 2, lb = l & 3;

    const int abase = kq * 16 * 128 + mtile * 64 + la * 4 + lb;   // uint4 idx
    const uint4* wsB = ws4 + kq * 16 * 128 + (npair * 16 + la) * 4 + lb;

    const int tile = mtile * 2 + npair;
    float* rp = red + (kq * 4 + tile) * 288;

    // pointwise mapping (tid < 256): unit u, batch b  (coalesced g_P/out)
    const int pu = tid & 7;
    const int pb = (tid & 255) >> 3;

    // h-production constants (even-pu threads write uint2)
    const int hup = pu >> 1;                               // unit pair 0..3
    const int hp  = (j0 >> 1) + hup;
    const int hks = hp >> 3, hq = hp & 7, hcc = hq & 3, hcb = hq >> 2;
    const int hidx4 = (hks * 4 + (pb >> 3)) * 32 + (pb & 7) * 4 + hcc;

    for (int t = 0; t < T_STEPS; t++) {
        // prefetch P gates (coalesced; hidden behind the mainloop)
        float pg[4];
        if (tid < 256) {
            #pragma unroll
            for (int g = 0; g < 4; g++)
                pg[g] = g_P[((size_t)t * BATCH + pb) * G4 + g * 1024 + j0 + pu];
        }

        const uint4* hb = g_hf + (t & 1) * 8192;

        float a0h[4] = {0,0,0,0}, a0l[4] = {0,0,0,0};
        float a1h[4] = {0,0,0,0}, a1l[4] = {0,0,0,0};

        uint4 A0[4], A1[4], B0[2], B1[2];
        #pragma unroll
        for (int i = 0; i < 4; i++) { A0[i] = hb[abase + i * 128]; A1[i] = hb[abase + i * 128 + 32]; }
        #pragma unroll
        for (int i = 0; i < 2; i++) { B0[i] = wsB[i * 128]; B1[i] = wsB[i * 128 + 32]; }

        #pragma unroll
        for (int ks = 0; ks < 16; ks++) {
            const int sa = ks & 3, sbx = ks & 1;
            uint4 ca0 = A0[sa], ca1 = A1[sa], cb0 = B0[sbx], cb1 = B1[sbx];
            int pa = ks + 4 < 16 ? ks + 4 : 15;
            A0[sa] = hb[abase + pa * 128];
            A1[sa] = hb[abase + pa * 128 + 32];
            int pbx = ks + 2 < 16 ? ks + 2 : 15;
            B0[sbx] = wsB[pbx * 128];
            B1[sbx] = wsB[pbx * 128 + 32];

            uint32_t ah[4] = {ca0.x, ca1.x, ca0.z, ca1.z};
            uint32_t al[4] = {ca0.y, ca1.y, ca0.w, ca1.w};
            uint32_t bh0[2] = {cb0.x, cb0.z}, bl0[2] = {cb0.y, cb0.w};
            uint32_t bh1[2] = {cb1.x, cb1.z}, bl1[2] = {cb1.y, cb1.w};

            mma_bf16(a0h, ah, bh0);
            mma_bf16(a1h, ah, bh1);
            mma_bf16(a0l, ah, bl0);
            mma_bf16(a1l, ah, bl1);
            mma_bf16(a0l, al, bh0);
            mma_bf16(a1l, al, bh1);
        }
        #pragma unroll
        for (int q = 0; q < 4; q++) { a0h[q] += a0l[q]; a1h[q] += a1l[q]; }

        // ---- write K-quarter partials ----
        *(float2*)&rp[la * 18 + 2 * lb]           = make_float2(a0h[0], a0h[1]);
        *(float2*)&rp[(la + 8) * 18 + 2 * lb]     = make_float2(a0h[2], a0h[3]);
        *(float2*)&rp[la * 18 + 8 + 2 * lb]       = make_float2(a1h[0], a1h[1]);
        *(float2*)&rp[(la + 8) * 18 + 8 + 2 * lb] = make_float2(a1h[2], a1h[3]);
        __syncthreads();

        // ---- pointwise LSTM cell + fused h production ----
        if (tid < 256) {
            float gate[4];
            const int rtile = (pb >> 4) * 2;
            const int rr = pb & 15;
            #pragma unroll
            for (int g = 0; g < 4; g++) {
                int cg = g * 8 + pu;
                int tl = rtile + (cg >> 4);
                int cc = cg & 15;
                float s = pg[g];
                #pragma unroll
                for (int k = 0; k < 4; k++)
                    s += red[(k * 4 + tl) * 288 + rr * 18 + cc];
                gate[g] = s;
            }
            int idx = (j0 + pu) * BATCH + pb;
            float co = g_c[idx];
            float cn = sigm(gate[1]) * co + sigm(gate[0]) * tanhf(gate[2]);
            float hnv = sigm(gate[3]) * tanhf(cn);
            g_c[idx] = cn;
            out[((size_t)t * BATCH + pb) * HID + j0 + pu] = hnv;

            // pair exchange: even-pu thread gets odd-pu partner's h (same warp)
            float hpart = __shfl_down_sync(0xFFFFFFFFu, hnv, 1);
            if ((pu & 1) == 0) {
                unsigned short h0h, h0l, h1h, h1l;
                bf16split(hnv,   h0h, h0l);
                bf16split(hpart, h1h, h1l);
                uint32_t hi2 = (uint32_t)h0h | ((uint32_t)h1h << 16);
                uint32_t lo2 = (uint32_t)h0l | ((uint32_t)h1l << 16);
                uint2* dst = (uint2*)&g_hf[((t + 1) & 1) * 8192 + hidx4] + hcb;
                *dst = make_uint2(hi2, lo2);
            }
        }

        grid_sync();
    }
}

// ---------------- launch ----------------
extern "C" void kernel_launch(void* const* d_in, const int* in_sizes, int n_in,
                              void* d_out, int out_size) {
    const float* x  = (const float*)d_in[0];   // [T,B,D]
    const float* Wx = (const float*)d_in[1];   // [D,4H]
    const float* Wh = (const float*)d_in[2];   // [H,4H]
    const float* b  = (const float*)d_in[3];   // [4H]
    float* out = (float*)d_out;                // [T,B,H]

    cudaFuncSetAttribute(sgemm_bf16, cudaFuncAttributeMaxDynamicSharedMemorySize, GS_SMEM);
    cudaFuncSetAttribute(lstm_persist, cudaFuncAttributeMaxDynamicSharedMemorySize, SMEM_BYTES);

    init_state<<<256, 256>>>();
    phase_pad<<<1, 32>>>();   // shifts ncu capture (4th launch) onto lstm_persist

    dim3 gg(G4 / 128, M_TOT / 128);   // (32, 32)
    sgemm_bf16<<<gg, 256, GS_SMEM>>>(x, Wx, b);

    lstm_persist<<<NBLK, NTHR, SMEM_BYTES>>>(Wh, out);
}

// round 16
// speedup vs baseline: 4.6148x; 1.0064x over previous
#include <cuda_runtime.h>
#include <cuda_bf16.h>
#include <cstdint>

#define T_STEPS 128
#define BATCH   32
#define DIM     1024
#define HID     1024
#define G4      4096            // 4*HID
#define M_TOT   4096            // T_STEPS*BATCH
#define NBLK    128             // persistent blocks (<= 148 SMs, 1 block/SM)
#define NTHR    512

// ---------------- device scratch (no allocations allowed) ----------------
__device__ float g_P[(size_t)M_TOT * G4];   // 64MB: x@Wx + b
// h split to bf16 hi/lo, fragment-major, double buffered.
// uint4 index: [(ks*4 + (b>>3))*32 + (b&7)*4 + cc]  (8192 uint4 per buffer)
// uint4 = {hi2(p0), lo2(p0), hi2(p1), lo2(p1)}, p0 = 8ks+cc, p1 = p0+4 (kpair ids)
__device__ uint4 g_hf[2 * 8192];
__device__ float g_c[HID * BATCH];          // cell state [unit][batch]
__device__ unsigned g_cnt = 0;
__device__ volatile unsigned g_gen = 0;

// ---------------- helpers ----------------
__device__ __forceinline__ float sigm(float x) { return 1.f / (1.f + __expf(-x)); }

__device__ __forceinline__ void mma_bf16(float* d, const uint32_t* a, const uint32_t* b) {
    asm volatile("mma.sync.aligned.m16n8k16.row.col.f32.bf16.bf16.f32 "
                 "{%0,%1,%2,%3}, {%4,%5,%6,%7}, {%8,%9}, {%0,%1,%2,%3};"
                 : "+f"(d[0]), "+f"(d[1]), "+f"(d[2]), "+f"(d[3])
                 : "r"(a[0]), "r"(a[1]), "r"(a[2]), "r"(a[3]), "r"(b[0]), "r"(b[1]));
}
__device__ __forceinline__ void bf16split(float v, unsigned short& h, unsigned short& l) {
    __nv_bfloat16 hb = __float2bfloat16(v);
    __nv_bfloat16 lb = __float2bfloat16(v - __bfloat162float(hb));
    h = *(unsigned short*)&hb;
    l = *(unsigned short*)&lb;
}

// ---------------- software grid barrier ----------------
__device__ __forceinline__ void grid_sync() {
    __threadfence();              // release + L1D invalidate (CCTL.IVALL at gpu scope)
    __syncthreads();
    if (threadIdx.x == 0) {
        unsigned gen = g_gen;
        if (atomicAdd(&g_cnt, 1u) == NBLK - 1u) {
            g_cnt = 0;
            __threadfence();
            g_gen = gen + 1;
        } else {
            while (g_gen == gen) { }
        }
    }
    __syncthreads();
}

// ---------------- init: zero states ----------------
__global__ void init_state() {
    int i = blockIdx.x * blockDim.x + threadIdx.x;
    if (i < 2 * 8192) g_hf[i] = make_uint4(0, 0, 0, 0);
    if (i < HID * BATCH) g_c[i] = 0.f;
}

// ---------------- dummy: shifts the ncu capture window (4th launch = lstm_persist) ----------------
__global__ void phase_pad() {}

// ---------------- bf16 split-precision GEMM via mma.sync (R8, verified) ----------------
#define GPITCH 40
#define GAREA  (128 * GPITCH * 2)
#define GBUF   (4 * GAREA)
#define GS_SMEM (2 * GBUF)

__global__ __launch_bounds__(256) void sgemm_bf16(const float* __restrict__ A,
                                                  const float* __restrict__ B,
                                                  const float* __restrict__ bias) {
    extern __shared__ char gsm_[];
    const int tid = threadIdx.x;
    const int l   = tid & 31;
    const int wid = tid >> 5;
    const int wm  = wid >> 2, wn = wid & 3;
    const int brow = blockIdx.y, bcol = blockIdx.x;

    float4 ra[4], rb[4];

    auto ldg_slab = [&](int s) {
        const int k0 = s * 32;
        #pragma unroll
        for (int i = 0; i < 4; i++) {
            int id = tid + i * 256;
            int row = id >> 3, q = id & 7;
            ra[i] = *(const float4*)(A + (size_t)(brow * 128 + row) * DIM + k0 + q * 4);
            int k = id & 31, n4 = (id >> 5) * 4;
            rb[i] = *(const float4*)(B + (size_t)(k0 + k) * G4 + bcol * 128 + n4);
        }
    };
    auto sts_slab = [&](int b) {
        char* Ah = gsm_ + b * GBUF;
        char* Al = Ah + GAREA;
        char* Bh = Al + GAREA;
        char* Bl = Bh + GAREA;
        #pragma unroll
        for (int i = 0; i < 4; i++) {
            int id = tid + i * 256;
            int row = id >> 3, q = id & 7;
            float fa[4] = {ra[i].x, ra[i].y, ra[i].z, ra[i].w};
            ushort4 h4, l4;
            bf16split(fa[0], h4.x, l4.x); bf16split(fa[1], h4.y, l4.y);
            bf16split(fa[2], h4.z, l4.z); bf16split(fa[3], h4.w, l4.w);
            *(ushort4*)(Ah + row * (GPITCH * 2) + q * 8) = h4;
            *(ushort4*)(Al + row * (GPITCH * 2) + q * 8) = l4;
            int k = id & 31, n4 = (id >> 5) * 4;
            float fb[4] = {rb[i].x, rb[i].y, rb[i].z, rb[i].w};
            #pragma unroll
            for (int j = 0; j < 4; j++) {
                unsigned short h, lo;
                bf16split(fb[j], h, lo);
                *(unsigned short*)(Bh + (n4 + j) * (GPITCH * 2) + k * 2) = h;
                *(unsigned short*)(Bl + (n4 + j) * (GPITCH * 2) + k * 2) = lo;
            }
        }
    };

    float acc[4][4][4];
    #pragma unroll
    for (int mi = 0; mi < 4; mi++)
        #pragma unroll
        for (int ni = 0; ni < 4; ni++)
            #pragma unroll
            for (int q = 0; q < 4; q++) acc[mi][ni][q] = 0.f;

    ldg_slab(0);
    sts_slab(0);
    __syncthreads();

    for (int s = 0; s < 32; s++) {
        if (s < 31) ldg_slab(s + 1);

        const int b = s & 1;
        const char* Ah = gsm_ + b * GBUF;
        const char* Al = Ah + GAREA;
        const char* Bh = Al + GAREA;
        const char* Bl = Bh + GAREA;

        #pragma unroll
        for (int ks = 0; ks < 2; ks++) {
            const int kb = ks * 32 + (l & 3) * 4;
            uint32_t ah[4][4], al[4][4], bh[4][2], bl[4][2];
            #pragma unroll
            for (int mi = 0; mi < 4; mi++) {
                const char* p = Ah + (wm * 64 + mi * 16 + (l >> 2)) * (GPITCH * 2) + kb;
                const char* q = Al + (wm * 64 + mi * 16 + (l >> 2)) * (GPITCH * 2) + kb;
                ah[mi][0] = *(const uint32_t*)(p);
                ah[mi][1] = *(const uint32_t*)(p + 8 * GPITCH * 2);
                ah[mi][2] = *(const uint32_t*)(p + 16);
                ah[mi][3] = *(const uint32_t*)(p + 8 * GPITCH * 2 + 16);
                al[mi][0] = *(const uint32_t*)(q);
                al[mi][1] = *(const uint32_t*)(q + 8 * GPITCH * 2);
                al[mi][2] = *(const uint32_t*)(q + 16);
                al[mi][3] = *(const uint32_t*)(q + 8 * GPITCH * 2 + 16);
            }
            #pragma unroll
            for (int ni = 0; ni < 4; ni++) {
                const char* p = Bh + (wn * 32 + ni * 8 + (l >> 2)) * (GPITCH * 2) + kb;
                const char* q = Bl + (wn * 32 + ni * 8 + (l >> 2)) * (GPITCH * 2) + kb;
                bh[ni][0] = *(const uint32_t*)(p);
                bh[ni][1] = *(const uint32_t*)(p + 16);
                bl[ni][0] = *(const uint32_t*)(q);
                bl[ni][1] = *(const uint32_t*)(q + 16);
            }
            #pragma unroll
            for (int mi = 0; mi < 4; mi++)
                #pragma unroll
                for (int ni = 0; ni < 4; ni++) {
                    mma_bf16(acc[mi][ni], ah[mi], bh[ni]);
                    mma_bf16(acc[mi][ni], ah[mi], bl[ni]);
                    mma_bf16(acc[mi][ni], al[mi], bh[ni]);
                }
        }
        __syncthreads();
        if (s < 31) {
            sts_slab((s + 1) & 1);
            __syncthreads();
        }
    }

    #pragma unroll
    for (int mi = 0; mi < 4; mi++) {
        int row0 = brow * 128 + wm * 64 + mi * 16 + (l >> 2);
        #pragma unroll
        for (int ni = 0; ni < 4; ni++) {
            int col = bcol * 128 + wn * 32 + ni * 8 + 2 * (l & 3);
            float b0 = bias[col], b1 = bias[col + 1];
            float2 v0 = make_float2(acc[mi][ni][0] + b0, acc[mi][ni][1] + b1);
            float2 v1 = make_float2(acc[mi][ni][2] + b0, acc[mi][ni][3] + b1);
            *(float2*)&g_P[(size_t)row0 * G4 + col]       = v0;
            *(float2*)&g_P[(size_t)(row0 + 8) * G4 + col] = v1;
        }
    }
}

// ---------------- persistent LSTM with tensor-core recurrent GEMM ----------------
// 128 blocks x 512 threads (16 warps). Block owns 8 hidden units (32 gate cols).
// Warp = (kq 0..7, mtile 0..1): 16 batch-rows x ALL 32 cols over K=128 (8 ksteps),
// 8-way K reduce. Per iteration: 2 LDG.128 (A, no duplication) + 4 LDS.128 (B)
// + 12 MMAs. A depth-4 prefetch, B depth-2. Merged hi/lo accumulators.
#define WS_U4   8192                         // Wh fragments (128KB)
#define REDT    576                          // per (kq,mtile) tile: 16 rows x pitch 36
#define RED_F   (16 * REDT)                  // 36,864B
#define SMEM_BYTES (WS_U4 * 16 + RED_F * 4)

__global__ __launch_bounds__(NTHR, 1) void lstm_persist(const float* __restrict__ Wh,
                                                        float* __restrict__ out) {
    extern __shared__ char sm[];
    uint4* ws4 = (uint4*)sm;                 // Wh fragments: [ks 0..63][n*4+cc] uint4
    float* red = (float*)(ws4 + WS_U4);      // [(kq*2+mtile)][16][36]

    const int tid = threadIdx.x;
    const int j0  = blockIdx.x * 8;

    // ---- build Wh fragment smem once: element (k, n) ----
    for (int i = 0; i < 64; i++) {
        int idx = tid + i * NTHR;            // 0..32767
        int n = idx & 31, k = idx >> 5;
        float v = Wh[(size_t)k * G4 + (n >> 3) * 1024 + j0 + (n & 7)];
        unsigned short hi, lo;
        bf16split(v, hi, lo);
        int p = k >> 1, ks = p >> 3, q = p & 7, cc = q & 3, cb = q >> 2;
        char* base = (char*)(ws4 + ks * 128 + n * 4 + cc) + cb * 8 + (k & 1) * 2;
        *(unsigned short*)(base)     = hi;
        *(unsigned short*)(base + 4) = lo;
    }
    __syncthreads();

    const int wid = tid >> 5, l = tid & 31;
    const int kq    = wid & 7;               // K chunk: ksteps kq*8 .. kq*8+8
    const int mtile = wid >> 3;              // batch rows 16*mtile..
    const int la = l >> 2, lb = l & 3;

    const int abase = kq * 8 * 128 + mtile * 64 + la * 4 + lb;    // uint4 idx
    const uint4* wsB = ws4 + kq * 8 * 128 + la * 4 + lb;          // + nt*32 per n-tile

    float* rp = red + (kq * 2 + mtile) * REDT;

    // pointwise mapping (tid < 256): unit u, batch b  (coalesced g_P/out)
    const int pu = tid & 7;
    const int pb = (tid & 255) >> 3;

    // h-production constants (even-pu threads write uint2)
    const int hup = pu >> 1;                               // unit pair 0..3
    const int hp  = (j0 >> 1) + hup;
    const int hks = hp >> 3, hq = hp & 7, hcc = hq & 3, hcb = hq >> 2;
    const int hidx4 = (hks * 4 + (pb >> 3)) * 32 + (pb & 7) * 4 + hcc;

    for (int t = 0; t < T_STEPS; t++) {
        // prefetch P gates (coalesced; hidden behind the mainloop)
        float pg[4];
        if (tid < 256) {
            #pragma unroll
            for (int g = 0; g < 4; g++)
                pg[g] = g_P[((size_t)t * BATCH + pb) * G4 + g * 1024 + j0 + pu];
        }

        const uint4* hb = g_hf + (t & 1) * 8192;

        float acc[4][4];
        #pragma unroll
        for (int nt = 0; nt < 4; nt++)
            #pragma unroll
            for (int q = 0; q < 4; q++) acc[nt][q] = 0.f;

        uint4 A0[4], A1[4], Bb[2][4];
        #pragma unroll
        for (int i = 0; i < 4; i++) { A0[i] = hb[abase + i * 128]; A1[i] = hb[abase + i * 128 + 32]; }
        #pragma unroll
        for (int i = 0; i < 2; i++)
            #pragma unroll
            for (int nt = 0; nt < 4; nt++) Bb[i][nt] = wsB[i * 128 + nt * 32];

        #pragma unroll
        for (int ks = 0; ks < 8; ks++) {
            const int sa = ks & 3, sbx = ks & 1;
            uint4 ca0 = A0[sa], ca1 = A1[sa];
            uint4 cB[4];
            #pragma unroll
            for (int nt = 0; nt < 4; nt++) cB[nt] = Bb[sbx][nt];

            int pa = ks + 4 < 8 ? ks + 4 : 7;
            A0[sa] = hb[abase + pa * 128];
            A1[sa] = hb[abase + pa * 128 + 32];
            int pbx = ks + 2 < 8 ? ks + 2 : 7;
            #pragma unroll
            for (int nt = 0; nt < 4; nt++) Bb[sbx][nt] = wsB[pbx * 128 + nt * 32];

            uint32_t ah[4] = {ca0.x, ca1.x, ca0.z, ca1.z};
            uint32_t al[4] = {ca0.y, ca1.y, ca0.w, ca1.w};
            #pragma unroll
            for (int nt = 0; nt < 4; nt++) {
                uint32_t bh[2] = {cB[nt].x, cB[nt].z};
                uint32_t bl[2] = {cB[nt].y, cB[nt].w};
                mma_bf16(acc[nt], ah, bh);
                mma_bf16(acc[nt], ah, bl);
                mma_bf16(acc[nt], al, bh);
            }
        }

        // ---- write K-chunk partials: rows la/la+8, cols nt*8 + 2lb ----
        #pragma unroll
        for (int nt = 0; nt < 4; nt++) {
            *(float2*)&rp[la * 36 + nt * 8 + 2 * lb]       = make_float2(acc[nt][0], acc[nt][1]);
            *(float2*)&rp[(la + 8) * 36 + nt * 8 + 2 * lb] = make_float2(acc[nt][2], acc[nt][3]);
        }
        __syncthreads();

        // ---- pointwise LSTM cell + fused h production ----
        if (tid < 256) {
            const int rbase = (pb >> 4) * REDT + (pb & 15) * 36;   // mtile tile, row
            float gate[4];
            #pragma unroll
            for (int g = 0; g < 4; g++) {
                int cg = g * 8 + pu;
                float s = pg[g];
                #pragma unroll
                for (int k = 0; k < 8; k++)
                    s += red[k * 2 * REDT + rbase + cg];
                gate[g] = s;
            }
            int idx = (j0 + pu) * BATCH + pb;
            float co = g_c[idx];
            float cn = sigm(gate[1]) * co + sigm(gate[0]) * tanhf(gate[2]);
            float hnv = sigm(gate[3]) * tanhf(cn);
            g_c[idx] = cn;
            out[((size_t)t * BATCH + pb) * HID + j0 + pu] = hnv;

            // pair exchange: even-pu thread gets odd-pu partner's h (same warp)
            float hpart = __shfl_down_sync(0xFFFFFFFFu, hnv, 1);
            if ((pu & 1) == 0) {
                unsigned short h0h, h0l, h1h, h1l;
                bf16split(hnv,   h0h, h0l);
                bf16split(hpart, h1h, h1l);
                uint32_t hi2 = (uint32_t)h0h | ((uint32_t)h1h << 16);
                uint32_t lo2 = (uint32_t)h0l | ((uint32_t)h1l << 16);
                uint2* dst = (uint2*)&g_hf[((t + 1) & 1) * 8192 + hidx4] + hcb;
                *dst = make_uint2(hi2, lo2);
            }
        }

        grid_sync();
    }
}

// ---------------- launch ----------------
extern "C" void kernel_launch(void* const* d_in, const int* in_sizes, int n_in,
                              void* d_out, int out_size) {
    const float* x  = (const float*)d_in[0];   // [T,B,D]
    const float* Wx = (const float*)d_in[1];   // [D,4H]
    const float* Wh = (const float*)d_in[2];   // [H,4H]
    const float* b  = (const float*)d_in[3];   // [4H]
    float* out = (float*)d_out;                // [T,B,H]

    cudaFuncSetAttribute(sgemm_bf16, cudaFuncAttributeMaxDynamicSharedMemorySize, GS_SMEM);
    cudaFuncSetAttribute(lstm_persist, cudaFuncAttributeMaxDynamicSharedMemorySize, SMEM_BYTES);

    init_state<<<256, 256>>>();
    phase_pad<<<1, 32>>>();   // shifts ncu capture (4th launch) onto lstm_persist

    dim3 gg(G4 / 128, M_TOT / 128);   // (32, 32)
    sgemm_bf16<<<gg, 256, GS_SMEM>>>(x, Wx, b);

    lstm_persist<<<NBLK, NTHR, SMEM_BYTES>>>(Wh, out);
}

// round 17
// speedup vs baseline: 4.6347x; 1.0043x over previous
#include <cuda_runtime.h>
#include <cuda_bf16.h>
#include <cstdint>

#define T_STEPS 128
#define BATCH   32
#define DIM     1024
#define HID     1024
#define G4      4096            // 4*HID
#define M_TOT   4096            // T_STEPS*BATCH
#define NBLK    128             // persistent blocks (<= 148 SMs, 1 block/SM)
#define NTHR    512

// ---------------- device scratch (no allocations allowed) ----------------
__device__ float g_P[(size_t)M_TOT * G4];   // 64MB: x@Wx + b
// h split to bf16 hi/lo, fragment-major, double buffered.
// uint4 index: [(ks*4 + (b>>3))*32 + (b&7)*4 + cc]  (8192 uint4 per buffer)
// uint4 = {hi2(p0), lo2(p0), hi2(p1), lo2(p1)}, p0 = 8ks+cc, p1 = p0+4 (kpair ids)
__device__ uint4 g_hf[2 * 8192];
__device__ unsigned g_flags[NBLK * 32];     // per-block arrival flags (128B stride)
__device__ volatile unsigned g_gen = 0;     // release counter (monotonic per launch)

// ---------------- helpers ----------------
__device__ __forceinline__ float sigm(float x) { return 1.f / (1.f + __expf(-x)); }

__device__ __forceinline__ void mma_bf16(float* d, const uint32_t* a, const uint32_t* b) {
    asm volatile("mma.sync.aligned.m16n8k16.row.col.f32.bf16.bf16.f32 "
                 "{%0,%1,%2,%3}, {%4,%5,%6,%7}, {%8,%9}, {%0,%1,%2,%3};"
                 : "+f"(d[0]), "+f"(d[1]), "+f"(d[2]), "+f"(d[3])
                 : "r"(a[0]), "r"(a[1]), "r"(a[2]), "r"(a[3]), "r"(b[0]), "r"(b[1]));
}
__device__ __forceinline__ void bf16split(float v, unsigned short& h, unsigned short& l) {
    __nv_bfloat16 hb = __float2bfloat16(v);
    __nv_bfloat16 lb = __float2bfloat16(v - __bfloat162float(hb));
    h = *(unsigned short*)&hb;
    l = *(unsigned short*)&lb;
}

// ---------------- flag-tree grid barrier (no atomics) ----------------
// Arrival: one volatile STG per block to a 128B-strided slot.
// Block 0: 128 threads poll the 128 flags in parallel, then publish g_gen.
// Others: poll g_gen. Targets are absolute (t+1); init_state zeroes per launch.
__device__ __forceinline__ void grid_sync_step(int t, int tid) {
    __threadfence();              // release + L1D invalidate (CCTL.IVALL at gpu scope)
    __syncthreads();
    volatile unsigned* fl = (volatile unsigned*)g_flags;
    const unsigned tgt = (unsigned)(t + 1);
    if (tid == 0) fl[blockIdx.x * 32] = tgt;
    if (blockIdx.x == 0) {
        if (tid < NBLK) {
            while (fl[tid * 32] < tgt) { }
        }
        __syncthreads();          // all 128 flags observed
        if (tid == 0) g_gen = tgt;
    } else {
        if (tid == 0) {
            while (g_gen < tgt) { }
        }
        __syncthreads();
    }
}

// ---------------- init: zero states + barrier (per launch, graph-replay safe) ----------------
__global__ void init_state() {
    int i = blockIdx.x * blockDim.x + threadIdx.x;
    if (i < 2 * 8192) g_hf[i] = make_uint4(0, 0, 0, 0);
    if (i < NBLK * 32) g_flags[i] = 0;
    if (i == 0) g_gen = 0;
}

// ---------------- dummy: shifts the ncu capture window (4th launch = lstm_persist) ----------------
__global__ void phase_pad() {}

// ---------------- bf16 split-precision GEMM via mma.sync (R8, verified) ----------------
#define GPITCH 40
#define GAREA  (128 * GPITCH * 2)
#define GBUF   (4 * GAREA)
#define GS_SMEM (2 * GBUF)

__global__ __launch_bounds__(256) void sgemm_bf16(const float* __restrict__ A,
                                                  const float* __restrict__ B,
                                                  const float* __restrict__ bias) {
    extern __shared__ char gsm_[];
    const int tid = threadIdx.x;
    const int l   = tid & 31;
    const int wid = tid >> 5;
    const int wm  = wid >> 2, wn = wid & 3;
    const int brow = blockIdx.y, bcol = blockIdx.x;

    float4 ra[4], rb[4];

    auto ldg_slab = [&](int s) {
        const int k0 = s * 32;
        #pragma unroll
        for (int i = 0; i < 4; i++) {
            int id = tid + i * 256;
            int row = id >> 3, q = id & 7;
            ra[i] = *(const float4*)(A + (size_t)(brow * 128 + row) * DIM + k0 + q * 4);
            int k = id & 31, n4 = (id >> 5) * 4;
            rb[i] = *(const float4*)(B + (size_t)(k0 + k) * G4 + bcol * 128 + n4);
        }
    };
    auto sts_slab = [&](int b) {
        char* Ah = gsm_ + b * GBUF;
        char* Al = Ah + GAREA;
        char* Bh = Al + GAREA;
        char* Bl = Bh + GAREA;
        #pragma unroll
        for (int i = 0; i < 4; i++) {
            int id = tid + i * 256;
            int row = id >> 3, q = id & 7;
            float fa[4] = {ra[i].x, ra[i].y, ra[i].z, ra[i].w};
            ushort4 h4, l4;
            bf16split(fa[0], h4.x, l4.x); bf16split(fa[1], h4.y, l4.y);
            bf16split(fa[2], h4.z, l4.z); bf16split(fa[3], h4.w, l4.w);
            *(ushort4*)(Ah + row * (GPITCH * 2) + q * 8) = h4;
            *(ushort4*)(Al + row * (GPITCH * 2) + q * 8) = l4;
            int k = id & 31, n4 = (id >> 5) * 4;
            float fb[4] = {rb[i].x, rb[i].y, rb[i].z, rb[i].w};
            #pragma unroll
            for (int j = 0; j < 4; j++) {
                unsigned short h, lo;
                bf16split(fb[j], h, lo);
                *(unsigned short*)(Bh + (n4 + j) * (GPITCH * 2) + k * 2) = h;
                *(unsigned short*)(Bl + (n4 + j) * (GPITCH * 2) + k * 2) = lo;
            }
        }
    };

    float acc[4][4][4];
    #pragma unroll
    for (int mi = 0; mi < 4; mi++)
        #pragma unroll
        for (int ni = 0; ni < 4; ni++)
            #pragma unroll
            for (int q = 0; q < 4; q++) acc[mi][ni][q] = 0.f;

    ldg_slab(0);
    sts_slab(0);
    __syncthreads();

    for (int s = 0; s < 32; s++) {
        if (s < 31) ldg_slab(s + 1);

        const int b = s & 1;
        const char* Ah = gsm_ + b * GBUF;
        const char* Al = Ah + GAREA;
        const char* Bh = Al + GAREA;
        const char* Bl = Bh + GAREA;

        #pragma unroll
        for (int ks = 0; ks < 2; ks++) {
            const int kb = ks * 32 + (l & 3) * 4;
            uint32_t ah[4][4], al[4][4], bh[4][2], bl[4][2];
            #pragma unroll
            for (int mi = 0; mi < 4; mi++) {
                const char* p = Ah + (wm * 64 + mi * 16 + (l >> 2)) * (GPITCH * 2) + kb;
                const char* q = Al + (wm * 64 + mi * 16 + (l >> 2)) * (GPITCH * 2) + kb;
                ah[mi][0] = *(const uint32_t*)(p);
                ah[mi][1] = *(const uint32_t*)(p + 8 * GPITCH * 2);
                ah[mi][2] = *(const uint32_t*)(p + 16);
                ah[mi][3] = *(const uint32_t*)(p + 8 * GPITCH * 2 + 16);
                al[mi][0] = *(const uint32_t*)(q);
                al[mi][1] = *(const uint32_t*)(q + 8 * GPITCH * 2);
                al[mi][2] = *(const uint32_t*)(q + 16);
                al[mi][3] = *(const uint32_t*)(q + 8 * GPITCH * 2 + 16);
            }
            #pragma unroll
            for (int ni = 0; ni < 4; ni++) {
                const char* p = Bh + (wn * 32 + ni * 8 + (l >> 2)) * (GPITCH * 2) + kb;
                const char* q = Bl + (wn * 32 + ni * 8 + (l >> 2)) * (GPITCH * 2) + kb;
                bh[ni][0] = *(const uint32_t*)(p);
                bh[ni][1] = *(const uint32_t*)(p + 16);
                bl[ni][0] = *(const uint32_t*)(q);
                bl[ni][1] = *(const uint32_t*)(q + 16);
            }
            #pragma unroll
            for (int mi = 0; mi < 4; mi++)
                #pragma unroll
                for (int ni = 0; ni < 4; ni++) {
                    mma_bf16(acc[mi][ni], ah[mi], bh[ni]);
                    mma_bf16(acc[mi][ni], ah[mi], bl[ni]);
                    mma_bf16(acc[mi][ni], al[mi], bh[ni]);
                }
        }
        __syncthreads();
        if (s < 31) {
            sts_slab((s + 1) & 1);
            __syncthreads();
        }
    }

    #pragma unroll
    for (int mi = 0; mi < 4; mi++) {
        int row0 = brow * 128 + wm * 64 + mi * 16 + (l >> 2);
        #pragma unroll
        for (int ni = 0; ni < 4; ni++) {
            int col = bcol * 128 + wn * 32 + ni * 8 + 2 * (l & 3);
            float b0 = bias[col], b1 = bias[col + 1];
            float2 v0 = make_float2(acc[mi][ni][0] + b0, acc[mi][ni][1] + b1);
            float2 v1 = make_float2(acc[mi][ni][2] + b0, acc[mi][ni][3] + b1);
            *(float2*)&g_P[(size_t)row0 * G4 + col]       = v0;
            *(float2*)&g_P[(size_t)(row0 + 8) * G4 + col] = v1;
        }
    }
}

// ---------------- persistent LSTM with tensor-core recurrent GEMM ----------------
// 128 blocks x 512 threads (16 warps). Block owns 8 hidden units (32 gate cols).
// Warp = (kq 0..7, mtile 0..1): 16 batch-rows x ALL 32 cols over K=128 (8 ksteps),
// 8-way K reduce. Cell state lives in registers (owning thread is time-invariant).
#define WS_U4   8192                         // Wh fragments (128KB)
#define REDT    576                          // per (kq,mtile) tile: 16 rows x pitch 36
#define RED_F   (16 * REDT)                  // 36,864B
#define SMEM_BYTES (WS_U4 * 16 + RED_F * 4)

__global__ __launch_bounds__(NTHR, 1) void lstm_persist(const float* __restrict__ Wh,
                                                        float* __restrict__ out) {
    extern __shared__ char sm[];
    uint4* ws4 = (uint4*)sm;                 // Wh fragments: [ks 0..63][n*4+cc] uint4
    float* red = (float*)(ws4 + WS_U4);      // [(kq*2+mtile)][16][36]

    const int tid = threadIdx.x;
    const int j0  = blockIdx.x * 8;

    // ---- build Wh fragment smem once: element (k, n) ----
    for (int i = 0; i < 64; i++) {
        int idx = tid + i * NTHR;            // 0..32767
        int n = idx & 31, k = idx >> 5;
        float v = Wh[(size_t)k * G4 + (n >> 3) * 1024 + j0 + (n & 7)];
        unsigned short hi, lo;
        bf16split(v, hi, lo);
        int p = k >> 1, ks = p >> 3, q = p & 7, cc = q & 3, cb = q >> 2;
        char* base = (char*)(ws4 + ks * 128 + n * 4 + cc) + cb * 8 + (k & 1) * 2;
        *(unsigned short*)(base)     = hi;
        *(unsigned short*)(base + 4) = lo;
    }
    __syncthreads();

    const int wid = tid >> 5, l = tid & 31;
    const int kq    = wid & 7;               // K chunk: ksteps kq*8 .. kq*8+8
    const int mtile = wid >> 3;              // batch rows 16*mtile..
    const int la = l >> 2, lb = l & 3;

    const int abase = kq * 8 * 128 + mtile * 64 + la * 4 + lb;    // uint4 idx
    const uint4* wsB = ws4 + kq * 8 * 128 + la * 4 + lb;          // + nt*32 per n-tile

    float* rp = red + (kq * 2 + mtile) * REDT;

    // pointwise mapping (tid < 256): unit u, batch b  (coalesced g_P/out)
    const int pu = tid & 7;
    const int pb = (tid & 255) >> 3;
    float creg = 0.f;                        // cell state, register-resident all steps

    // h-production constants (even-pu threads write uint2)
    const int hup = pu >> 1;                               // unit pair 0..3
    const int hp  = (j0 >> 1) + hup;
    const int hks = hp >> 3, hq = hp & 7, hcc = hq & 3, hcb = hq >> 2;
    const int hidx4 = (hks * 4 + (pb >> 3)) * 32 + (pb & 7) * 4 + hcc;

    for (int t = 0; t < T_STEPS; t++) {
        // prefetch P gates (coalesced; hidden behind the mainloop)
        float pg[4];
        if (tid < 256) {
            #pragma unroll
            for (int g = 0; g < 4; g++)
                pg[g] = g_P[((size_t)t * BATCH + pb) * G4 + g * 1024 + j0 + pu];
        }

        const uint4* hb = g_hf + (t & 1) * 8192;

        float acc[4][4];
        #pragma unroll
        for (int nt = 0; nt < 4; nt++)
            #pragma unroll
            for (int q = 0; q < 4; q++) acc[nt][q] = 0.f;

        uint4 A0[4], A1[4], Bb[2][4];
        #pragma unroll
        for (int i = 0; i < 4; i++) { A0[i] = hb[abase + i * 128]; A1[i] = hb[abase + i * 128 + 32]; }
        #pragma unroll
        for (int i = 0; i < 2; i++)
            #pragma unroll
            for (int nt = 0; nt < 4; nt++) Bb[i][nt] = wsB[i * 128 + nt * 32];

        #pragma unroll
        for (int ks = 0; ks < 8; ks++) {
            const int sa = ks & 3, sbx = ks & 1;
            uint4 ca0 = A0[sa], ca1 = A1[sa];
            uint4 cB[4];
            #pragma unroll
            for (int nt = 0; nt < 4; nt++) cB[nt] = Bb[sbx][nt];

            int pa = ks + 4 < 8 ? ks + 4 : 7;
            A0[sa] = hb[abase + pa * 128];
            A1[sa] = hb[abase + pa * 128 + 32];
            int pbx = ks + 2 < 8 ? ks + 2 : 7;
            #pragma unroll
            for (int nt = 0; nt < 4; nt++) Bb[sbx][nt] = wsB[pbx * 128 + nt * 32];

            uint32_t ah[4] = {ca0.x, ca1.x, ca0.z, ca1.z};
            uint32_t al[4] = {ca0.y, ca1.y, ca0.w, ca1.w};
            #pragma unroll
            for (int nt = 0; nt < 4; nt++) {
                uint32_t bh[2] = {cB[nt].x, cB[nt].z};
                uint32_t bl[2] = {cB[nt].y, cB[nt].w};
                mma_bf16(acc[nt], ah, bh);
                mma_bf16(acc[nt], ah, bl);
                mma_bf16(acc[nt], al, bh);
            }
        }

        // ---- write K-chunk partials: rows la/la+8, cols nt*8 + 2lb ----
        #pragma unroll
        for (int nt = 0; nt < 4; nt++) {
            *(float2*)&rp[la * 36 + nt * 8 + 2 * lb]       = make_float2(acc[nt][0], acc[nt][1]);
            *(float2*)&rp[(la + 8) * 36 + nt * 8 + 2 * lb] = make_float2(acc[nt][2], acc[nt][3]);
        }
        __syncthreads();

        // ---- pointwise LSTM cell + fused h production ----
        if (tid < 256) {
            const int rbase = (pb >> 4) * REDT + (pb & 15) * 36;   // mtile tile, row
            float gate[4];
            #pragma unroll
            for (int g = 0; g < 4; g++) {
                int cg = g * 8 + pu;
                float s = pg[g];
                #pragma unroll
                for (int k = 0; k < 8; k++)
                    s += red[k * 2 * REDT + rbase + cg];
                gate[g] = s;
            }
            float cn = sigm(gate[1]) * creg + sigm(gate[0]) * tanhf(gate[2]);
            float hnv = sigm(gate[3]) * tanhf(cn);
            creg = cn;
            out[((size_t)t * BATCH + pb) * HID + j0 + pu] = hnv;

            // pair exchange: even-pu thread gets odd-pu partner's h (same warp)
            float hpart = __shfl_down_sync(0xFFFFFFFFu, hnv, 1);
            if ((pu & 1) == 0) {
                unsigned short h0h, h0l, h1h, h1l;
                bf16split(hnv,   h0h, h0l);
                bf16split(hpart, h1h, h1l);
                uint32_t hi2 = (uint32_t)h0h | ((uint32_t)h1h << 16);
                uint32_t lo2 = (uint32_t)h0l | ((uint32_t)h1l << 16);
                uint2* dst = (uint2*)&g_hf[((t + 1) & 1) * 8192 + hidx4] + hcb;
                *dst = make_uint2(hi2, lo2);
            }
        }

        grid_sync_step(t, tid);
    }
}

// ---------------- launch ----------------
extern "C" void kernel_launch(void* const* d_in, const int* in_sizes, int n_in,
                              void* d_out, int out_size) {
    const float* x  = (const float*)d_in[0];   // [T,B,D]
    const float* Wx = (const float*)d_in[1];   // [D,4H]
    const float* Wh = (const float*)d_in[2];   // [H,4H]
    const float* b  = (const float*)d_in[3];   // [4H]
    float* out = (float*)d_out;                // [T,B,H]

    cudaFuncSetAttribute(sgemm_bf16, cudaFuncAttributeMaxDynamicSharedMemorySize, GS_SMEM);
    cudaFuncSetAttribute(lstm_persist, cudaFuncAttributeMaxDynamicSharedMemorySize, SMEM_BYTES);

    init_state<<<256, 256>>>();
    phase_pad<<<1, 32>>>();   // shifts ncu capture (4th launch) onto lstm_persist

    dim3 gg(G4 / 128, M_TOT / 128);   // (32, 32)
    sgemm_bf16<<<gg, 256, GS_SMEM>>>(x, Wx, b);

    lstm_persist<<<NBLK, NTHR, SMEM_BYTES>>>(Wh, out);
}